// round 13
// baseline (speedup 1.0000x reference)
#include <cuda_runtime.h>
#include <cuda_bf16.h>
#include <cstdint>

#define B_    16
#define FIN_  256
#define NTOK_ 1024
#define NH_   8
#define FH_   64
#define CIN_  258
#define CPAD_ 288
#define COUT_ 512

typedef __nv_bfloat16 bf16;

// ---------------------------------------------------------------------------
__device__ bf16 g_t[B_ * NTOK_ * CPAD_];          // [b][n][c] padded to 288
__device__ bf16 g_w[3 * COUT_ * CPAD_];           // packed qkv weights
__device__ bf16 g_wo[FIN_ * COUT_];               // wo
__device__ bf16 g_q[B_ * NH_ * NTOK_ * FH_];      // [b][h][n][d]
__device__ bf16 g_k[B_ * NH_ * NTOK_ * FH_];      // [b][h][n][d]
__device__ bf16 g_v[B_ * NH_ * FH_ * NTOK_];      // [b][h][d][n]
__device__ bf16 g_o[B_ * NTOK_ * COUT_];          // [b][n][h*64+d]

// ---------------------------------------------------------------------------
__device__ __forceinline__ uint32_t smem_u32(const void* p) {
    uint32_t a;
    asm("{ .reg .u64 t; cvta.to.shared.u64 t, %1; cvt.u32.u64 %0, t; }" : "=r"(a) : "l"(p));
    return a;
}
__device__ __forceinline__ void cp16(uint32_t sdst, const void* gsrc) {
    asm volatile("cp.async.cg.shared.global [%0], [%1], 16;" :: "r"(sdst), "l"(gsrc));
}
#define CP_COMMIT() asm volatile("cp.async.commit_group;" ::: "memory")
#define CP_WAIT(n)  asm volatile("cp.async.wait_group %0;" :: "n"(n) : "memory")

__device__ __forceinline__ uint32_t pack2(float lo, float hi) {
    uint32_t r;
    asm("cvt.rn.bf16x2.f32 %0, %1, %2;" : "=r"(r) : "f"(hi), "f"(lo));
    return r;
}
__device__ __forceinline__ uint32_t ex2_bf16x2(uint32_t a) {
    uint32_t r;
    asm("ex2.approx.ftz.bf16x2 %0, %1;" : "=r"(r) : "r"(a));
    return r;
}
__device__ __forceinline__ void ldsm4(uint32_t r[4], uint32_t addr) {
    asm volatile("ldmatrix.sync.aligned.m8n8.x4.shared.b16 {%0,%1,%2,%3}, [%4];"
        : "=r"(r[0]), "=r"(r[1]), "=r"(r[2]), "=r"(r[3]) : "r"(addr));
}
__device__ __forceinline__ void mma16(float c[4], const uint32_t a[4], uint32_t b0, uint32_t b1) {
    asm volatile(
        "mma.sync.aligned.m16n8k16.row.col.f32.bf16.bf16.f32 "
        "{%0,%1,%2,%3}, {%4,%5,%6,%7}, {%8,%9}, {%0,%1,%2,%3};"
        : "+f"(c[0]), "+f"(c[1]), "+f"(c[2]), "+f"(c[3])
        : "r"(a[0]), "r"(a[1]), "r"(a[2]), "r"(a[3]), "r"(b0), "r"(b1));
}

// ---------------------------------------------------------------------------
// Kernel 0 (fused): prep t_T, pack qkv weights, pack wo.
__global__ __launch_bounds__(256) void prep_pack(
    const float* __restrict__ x,
    const float* __restrict__ wq, const float* __restrict__ wk, const float* __restrict__ wv,
    const float* __restrict__ wo)
{
    const int blk = blockIdx.x;
    if (blk < 512) {
        __shared__ float tile[32][33];
        const int nt = blk & 31, b = blk >> 5;
        const int tx = threadIdx.x & 31, ty = threadIdx.x >> 5;
        const int n0 = nt * 32;
        for (int c0 = 0; c0 < CPAD_; c0 += 32) {
            for (int ci = ty; ci < 32; ci += 8) {
                const int c = c0 + ci, n = n0 + tx;
                float v = 0.f;
                if (c < FIN_)           v = x[((size_t)b * FIN_ + c) * NTOK_ + n];
                else if (c == FIN_)     v = -1.f + (2.f / 31.f) * (float)(n >> 5);
                else if (c == FIN_ + 1) v = -1.f + (2.f / 31.f) * (float)(n & 31);
                tile[ci][tx] = v;
            }
            __syncthreads();
            for (int ni = ty; ni < 32; ni += 8)
                g_t[((size_t)b * NTOK_ + n0 + ni) * CPAD_ + c0 + tx] =
                    __float2bfloat16_rn(tile[tx][ni]);
            __syncthreads();
        }
    } else if (blk < 512 + 1728) {
        const int i = (blk - 512) * 256 + threadIdx.x;
        const int r = i / CPAD_, c = i - r * CPAD_;
        const int sel = r >> 9, o = r & 511;
        const float* w = (sel == 0) ? wq : ((sel == 1) ? wk : wv);
        g_w[i] = __float2bfloat16_rn((c < CIN_) ? w[o * CIN_ + c] : 0.f);
    } else {
        const int i = (blk - 512 - 1728) * 256 + threadIdx.x;
        g_wo[i] = __float2bfloat16_rn(wo[i]);
    }
}

// ---------------------------------------------------------------------------
// GEMM: CTA 128x128, 8 warps (4m x 2n), K-chunks 32 (2 k16 steps),
// 3-stage cp.async pipeline, one __syncthreads per chunk, ldmatrix fragments.
#define TSZB (128 * 80)
__global__ __launch_bounds__(256, 2) void qkv_gemm(
    const float* __restrict__ bq, const float* __restrict__ bk, const float* __restrict__ bv)
{
    extern __shared__ uint32_t sm[];
    const uint32_t sb = smem_u32(sm);

    const int tid = threadIdx.x;
    const int warp = tid >> 5, lane = tid & 31;
    const int g = lane >> 2, t4 = lane & 3;
    const int wm = warp & 3, wn = warp >> 2;
    const int nt = blockIdx.x, mt = blockIdx.y, b = blockIdx.z;
    const int sel = mt >> 2;
    const int o0 = (mt & 3) * 128;
    const int n0 = nt * 128;
    const bf16* wsrc = g_w + (size_t)(sel * COUT_ + o0) * CPAD_;
    const bf16* bsrc = g_t + ((size_t)b * NTOK_ + n0) * CPAD_;
    const float* bias = (sel == 0) ? bq : ((sel == 1) ? bk : bv);

    const uint32_t aoff = (uint32_t)((wm * 32 + (lane & 15)) * 80 + (lane >> 4) * 16);
    const uint32_t boff = (uint32_t)((wn * 64 + (lane >> 4) * 8 + (lane & 7)) * 80
                                     + ((lane >> 3) & 1) * 16);

    auto loadAB = [&](int kc, int st) {
        const uint32_t ab = sb + (uint32_t)(st * 2 * TSZB);
        const uint32_t bb = ab + TSZB;
        #pragma unroll
        for (int it = 0; it < 2; it++) {
            const int i = tid + it * 256;
            const int r = i >> 2, c4 = i & 3;
            cp16(ab + (uint32_t)(r * 80 + c4 * 16), wsrc + (size_t)r * CPAD_ + kc * 32 + c4 * 8);
            cp16(bb + (uint32_t)(r * 80 + c4 * 16), bsrc + (size_t)r * CPAD_ + kc * 32 + c4 * 8);
        }
    };

    float c[2][8][4];
    #pragma unroll
    for (int mi = 0; mi < 2; mi++)
        #pragma unroll
        for (int nf = 0; nf < 8; nf++)
            #pragma unroll
            for (int q = 0; q < 4; q++) c[mi][nf][q] = 0.f;

    loadAB(0, 0); CP_COMMIT();
    loadAB(1, 1); CP_COMMIT();

    const int NK = CPAD_ / 32;  // 9
    for (int kc = 0; kc < NK; kc++) {
        if (kc + 1 < NK) CP_WAIT(1); else CP_WAIT(0);
        __syncthreads();
        if (kc + 2 < NK) { loadAB(kc + 2, (kc + 2) % 3); CP_COMMIT(); }
        const uint32_t Ab = sb + (uint32_t)((kc % 3) * 2 * TSZB);
        const uint32_t Bb = Ab + TSZB;
        #pragma unroll
        for (int s = 0; s < 2; s++) {
            uint32_t a[2][4];
            ldsm4(a[0], Ab + aoff + s * 32);
            ldsm4(a[1], Ab + aoff + 16 * 80 + s * 32);
            #pragma unroll
            for (int nfp = 0; nfp < 4; nfp++) {
                uint32_t bb4[4];
                ldsm4(bb4, Bb + boff + nfp * 16 * 80 + s * 32);
                mma16(c[0][nfp * 2],     a[0], bb4[0], bb4[1]);
                mma16(c[1][nfp * 2],     a[1], bb4[0], bb4[1]);
                mma16(c[0][nfp * 2 + 1], a[0], bb4[2], bb4[3]);
                mma16(c[1][nfp * 2 + 1], a[1], bb4[2], bb4[3]);
            }
        }
    }
    __syncthreads();

    float* Cs = (float*)sm;   // staging reuse: 128*132*4 = 67584
    if (sel < 2) {
        #pragma unroll
        for (int mi = 0; mi < 2; mi++) {
            const int m0 = wm * 32 + mi * 16;
            const float bv0 = bias[o0 + m0 + g];
            const float bv1 = bias[o0 + m0 + g + 8];
            #pragma unroll
            for (int nf = 0; nf < 8; nf++) {
                const int nn = wn * 64 + nf * 8 + t4 * 2;
                Cs[(nn)     * 132 + m0 + g]     = c[mi][nf][0] + bv0;
                Cs[(nn + 1) * 132 + m0 + g]     = c[mi][nf][1] + bv0;
                Cs[(nn)     * 132 + m0 + g + 8] = c[mi][nf][2] + bv1;
                Cs[(nn + 1) * 132 + m0 + g + 8] = c[mi][nf][3] + bv1;
            }
        }
        __syncthreads();
        bf16* dstbase = (sel == 0) ? g_q : g_k;
        #pragma unroll
        for (int it = 0; it < 16; it++) {
            const int i = tid + it * 256;
            const int nl = i >> 5, m4 = i & 31;
            const float4 cv = *(const float4*)&Cs[nl * 132 + m4 * 4];
            const int o = o0 + m4 * 4;
            const int h = o >> 6, d = o & 63;
            uint2 pk = make_uint2(pack2(cv.x, cv.y), pack2(cv.z, cv.w));
            *(uint2*)&dstbase[(((size_t)b * NH_ + h) * NTOK_ + n0 + nl) * FH_ + d] = pk;
        }
    } else {
        #pragma unroll
        for (int mi = 0; mi < 2; mi++) {
            #pragma unroll
            for (int half = 0; half < 2; half++) {
                const int m = wm * 32 + mi * 16 + g + half * 8;
                const int o = o0 + m;
                const int h = o >> 6, d = o & 63;
                const float bval = bias[o];
                bf16* dst = g_v + (((size_t)b * NH_ + h) * FH_ + d) * NTOK_ + n0;
                #pragma unroll
                for (int nf = 0; nf < 8; nf++) {
                    const int nn = wn * 64 + nf * 8 + t4 * 2;
                    *(uint32_t*)&dst[nn] = pack2(c[mi][nf][half * 2] + bval,
                                                 c[mi][nf][half * 2 + 1] + bval);
                }
            }
        }
    }
}

// ---------------------------------------------------------------------------
// Kernel 2: attention. 128 threads, 4 warps, warp = 32 q rows (2 m-tiles).
// Each K/V ldmatrix feeds 4 MMAs -> fragment LDS traffic halved.
// Register-resident P, bf16x2 ex2, 3-buffer K/V, one barrier per chunk.
#define KVSTG 9216     // bytes per K or V stage
__global__ __launch_bounds__(128) void attn_kernel() {
    extern __shared__ uint32_t sm[];
    const uint32_t sb = smem_u32(sm);
    const uint32_t KsB = sb, VsB = sb + 3 * KVSTG;

    const int tid = threadIdx.x;
    const int warp = tid >> 5, lane = tid & 31;
    const int g = lane >> 2, t4 = lane & 3;
    const int m0 = warp * 32;          // 32 q rows per warp
    const int qt = blockIdx.x, h = blockIdx.y, b = blockIdx.z;
    const size_t hb = (size_t)(b * NH_ + h);
    const bf16* qsrc = g_q + hb * NTOK_ * FH_ + (size_t)qt * 128 * FH_;
    const bf16* ksrc = g_k + hb * NTOK_ * FH_;
    const bf16* vsrc = g_v + hb * FH_ * NTOK_;

    const uint32_t kvoff = (uint32_t)(((lane >> 4) * 8 + (lane & 7)) * 144
                                      + ((lane >> 3) & 1) * 16);

    // Q fragments: 2 m-tiles x 4 k16 steps
    uint32_t qf[2][4][4];
    #pragma unroll
    for (int mi = 0; mi < 2; mi++) {
        const uint32_t* q0 = (const uint32_t*)(qsrc + (size_t)(m0 + mi * 16 + g) * FH_);
        const uint32_t* q1 = (const uint32_t*)(qsrc + (size_t)(m0 + mi * 16 + g + 8) * FH_);
        #pragma unroll
        for (int s = 0; s < 4; s++) {
            qf[mi][s][0] = q0[s * 8 + t4];
            qf[mi][s][1] = q1[s * 8 + t4];
            qf[mi][s][2] = q0[s * 8 + t4 + 4];
            qf[mi][s][3] = q1[s * 8 + t4 + 4];
        }
    }

    auto loadKV = [&](int ck, int st) {
        const int c0 = ck * 64;
        #pragma unroll
        for (int it = 0; it < 4; it++) {
            const int i = tid + it * 128;
            const int r = i >> 3, c8 = i & 7;
            cp16(KsB + (uint32_t)(st * KVSTG + r * 144 + c8 * 16),
                 ksrc + (size_t)(c0 + r) * FH_ + c8 * 8);
            cp16(VsB + (uint32_t)(st * KVSTG + r * 144 + c8 * 16),
                 vsrc + (size_t)r * NTOK_ + c0 + c8 * 8);
        }
    };

    float oacc[2][8][4];
    #pragma unroll
    for (int mi = 0; mi < 2; mi++)
        #pragma unroll
        for (int nf = 0; nf < 8; nf++)
            #pragma unroll
            for (int q = 0; q < 4; q++) oacc[mi][nf][q] = 0.f;
    float lsum[2][2] = {{0.f, 0.f}, {0.f, 0.f}};

    loadKV(0, 0); CP_COMMIT();
    loadKV(1, 1); CP_COMMIT();

    const float SC = 0.125f * 1.4426950408889634f;   // 1/sqrt(64) * log2(e)

    for (int ck = 0; ck < 16; ck++) {
        if (ck + 1 < 16) CP_WAIT(1); else CP_WAIT(0);
        __syncthreads();
        if (ck + 2 < 16) { loadKV(ck + 2, (ck + 2) % 3); CP_COMMIT(); }
        const uint32_t Kb = KsB + (uint32_t)((ck % 3) * KVSTG);
        const uint32_t Vb = VsB + (uint32_t)((ck % 3) * KVSTG);

        // S = Q K^T : both m-tiles share each K fragment (1 ldsm : 4 mma)
        float sc[2][8][4];
        #pragma unroll
        for (int mi = 0; mi < 2; mi++)
            #pragma unroll
            for (int nf = 0; nf < 8; nf++)
                #pragma unroll
                for (int q = 0; q < 4; q++) sc[mi][nf][q] = 0.f;
        #pragma unroll
        for (int s = 0; s < 4; s++) {
            #pragma unroll
            for (int nfp = 0; nfp < 4; nfp++) {
                uint32_t bb4[4];
                ldsm4(bb4, Kb + kvoff + nfp * 16 * 144 + s * 32);
                mma16(sc[0][nfp * 2],     qf[0][s], bb4[0], bb4[1]);
                mma16(sc[0][nfp * 2 + 1], qf[0][s], bb4[2], bb4[3]);
                mma16(sc[1][nfp * 2],     qf[1][s], bb4[0], bb4[1]);
                mma16(sc[1][nfp * 2 + 1], qf[1][s], bb4[2], bb4[3]);
            }
        }

        // P = exp2(S*SC) in bf16x2 pairs (A-fragment layout)
        uint32_t pb[2][8][2];
        #pragma unroll
        for (int mi = 0; mi < 2; mi++)
            #pragma unroll
            for (int nf = 0; nf < 8; nf++) {
                pb[mi][nf][0] = ex2_bf16x2(pack2(sc[mi][nf][0] * SC, sc[mi][nf][1] * SC));
                pb[mi][nf][1] = ex2_bf16x2(pack2(sc[mi][nf][2] * SC, sc[mi][nf][3] * SC));
            }

        // O += P V^T : both m-tiles share each V fragment (1 ldsm : 4 mma)
        #pragma unroll
        for (int s = 0; s < 4; s++) {
            const uint32_t pa0[4] = { pb[0][2 * s][0], pb[0][2 * s][1],
                                      pb[0][2 * s + 1][0], pb[0][2 * s + 1][1] };
            const uint32_t pa1[4] = { pb[1][2 * s][0], pb[1][2 * s][1],
                                      pb[1][2 * s + 1][0], pb[1][2 * s + 1][1] };
            #pragma unroll
            for (int nfp = 0; nfp < 4; nfp++) {
                uint32_t bb4[4];
                ldsm4(bb4, Vb + kvoff + nfp * 16 * 144 + s * 32);
                mma16(oacc[0][nfp * 2],     pa0, bb4[0], bb4[1]);
                mma16(oacc[0][nfp * 2 + 1], pa0, bb4[2], bb4[3]);
                mma16(oacc[1][nfp * 2],     pa1, bb4[0], bb4[1]);
                mma16(oacc[1][nfp * 2 + 1], pa1, bb4[2], bb4[3]);
            }
        }

        // Row sums overlap in-flight O-MMAs
        #pragma unroll
        for (int mi = 0; mi < 2; mi++) {
            float s0 = 0.f, s1 = 0.f;
            #pragma unroll
            for (int nf = 0; nf < 8; nf++) {
                const float2 f0 = __bfloat1622float2(*(__nv_bfloat162*)&pb[mi][nf][0]);
                const float2 f1 = __bfloat1622float2(*(__nv_bfloat162*)&pb[mi][nf][1]);
                s0 += f0.x + f0.y;
                s1 += f1.x + f1.y;
            }
            s0 += __shfl_xor_sync(0xffffffffu, s0, 1);
            s0 += __shfl_xor_sync(0xffffffffu, s0, 2);
            s1 += __shfl_xor_sync(0xffffffffu, s1, 1);
            s1 += __shfl_xor_sync(0xffffffffu, s1, 2);
            lsum[mi][0] += s0;
            lsum[mi][1] += s1;
        }
    }

    // normalize + write g_o[b][n][h*64+d] (bf16 pairs)
    #pragma unroll
    for (int mi = 0; mi < 2; mi++) {
        const float inv0 = 1.f / lsum[mi][0], inv1 = 1.f / lsum[mi][1];
        bf16* d0 = g_o + ((size_t)b * NTOK_ + qt * 128 + m0 + mi * 16 + g) * COUT_ + h * FH_;
        bf16* d1 = d0 + 8 * COUT_;
        #pragma unroll
        for (int nf = 0; nf < 8; nf++) {
            const int dd = nf * 8 + t4 * 2;
            *(uint32_t*)&d0[dd] = pack2(oacc[mi][nf][0] * inv0, oacc[mi][nf][1] * inv0);
            *(uint32_t*)&d1[dd] = pack2(oacc[mi][nf][2] * inv1, oacc[mi][nf][3] * inv1);
        }
    }
}

// ---------------------------------------------------------------------------
// Kernel 3: output projection + bias + residual, 3-stage pipeline.
__global__ __launch_bounds__(256, 2) void oproj_gemm(
    const float* __restrict__ x, const float* __restrict__ bo, float* __restrict__ out)
{
    extern __shared__ uint32_t sm[];
    const uint32_t sb = smem_u32(sm);

    const int tid = threadIdx.x;
    const int warp = tid >> 5, lane = tid & 31;
    const int g = lane >> 2, t4 = lane & 3;
    const int wm = warp & 3, wn = warp >> 2;
    const int nt = blockIdx.x, mt = blockIdx.y, b = blockIdx.z;
    const int o0 = mt * 128, n0 = nt * 128;
    const bf16* asrc = g_wo + (size_t)o0 * COUT_;
    const bf16* bsrc = g_o + ((size_t)b * NTOK_ + n0) * COUT_;

    const uint32_t aoff = (uint32_t)((wm * 32 + (lane & 15)) * 80 + (lane >> 4) * 16);
    const uint32_t boff = (uint32_t)((wn * 64 + (lane >> 4) * 8 + (lane & 7)) * 80
                                     + ((lane >> 3) & 1) * 16);

    auto loadAB = [&](int kc, int st) {
        const uint32_t ab = sb + (uint32_t)(st * 2 * TSZB);
        const uint32_t bb = ab + TSZB;
        #pragma unroll
        for (int it = 0; it < 2; it++) {
            const int i = tid + it * 256;
            const int r = i >> 2, c4 = i & 3;
            cp16(ab + (uint32_t)(r * 80 + c4 * 16), asrc + (size_t)r * COUT_ + kc * 32 + c4 * 8);
            cp16(bb + (uint32_t)(r * 80 + c4 * 16), bsrc + (size_t)r * COUT_ + kc * 32 + c4 * 8);
        }
    };

    float c[2][8][4];
    #pragma unroll
    for (int mi = 0; mi < 2; mi++)
        #pragma unroll
        for (int nf = 0; nf < 8; nf++)
            #pragma unroll
            for (int q = 0; q < 4; q++) c[mi][nf][q] = 0.f;

    loadAB(0, 0); CP_COMMIT();
    loadAB(1, 1); CP_COMMIT();

    const int NK = 16;
    for (int kc = 0; kc < NK; kc++) {
        if (kc + 1 < NK) CP_WAIT(1); else CP_WAIT(0);
        __syncthreads();
        if (kc + 2 < NK) { loadAB(kc + 2, (kc + 2) % 3); CP_COMMIT(); }
        const uint32_t Ab = sb + (uint32_t)((kc % 3) * 2 * TSZB);
        const uint32_t Bb = Ab + TSZB;
        #pragma unroll
        for (int s = 0; s < 2; s++) {
            uint32_t a[2][4];
            ldsm4(a[0], Ab + aoff + s * 32);
            ldsm4(a[1], Ab + aoff + 16 * 80 + s * 32);
            #pragma unroll
            for (int nfp = 0; nfp < 4; nfp++) {
                uint32_t bb4[4];
                ldsm4(bb4, Bb + boff + nfp * 16 * 80 + s * 32);
                mma16(c[0][nfp * 2],     a[0], bb4[0], bb4[1]);
                mma16(c[1][nfp * 2],     a[1], bb4[0], bb4[1]);
                mma16(c[0][nfp * 2 + 1], a[0], bb4[2], bb4[3]);
                mma16(c[1][nfp * 2 + 1], a[1], bb4[2], bb4[3]);
            }
        }
    }

    #pragma unroll
    for (int mi = 0; mi < 2; mi++) {
        #pragma unroll
        for (int half = 0; half < 2; half++) {
            const int m = o0 + wm * 32 + mi * 16 + g + half * 8;
            const float bval = bo[m];
            const float* xr = x + ((size_t)b * FIN_ + m) * NTOK_ + n0;
            float* outr = out + ((size_t)b * FIN_ + m) * NTOK_ + n0;
            #pragma unroll
            for (int nf = 0; nf < 8; nf++) {
                const int nn = wn * 64 + nf * 8 + t4 * 2;
                const float2 xv = *(const float2*)&xr[nn];
                *(float2*)&outr[nn] = make_float2(xv.x + bval + c[mi][nf][half * 2],
                                                  xv.y + bval + c[mi][nf][half * 2 + 1]);
            }
        }
    }
}

// ---------------------------------------------------------------------------
extern "C" void kernel_launch(void* const* d_in, const int* in_sizes, int n_in,
                              void* d_out, int out_size)
{
    const float* x  = (const float*)d_in[0];
    const float* wq = (const float*)d_in[1];
    const float* bq = (const float*)d_in[2];
    const float* wk = (const float*)d_in[3];
    const float* bk = (const float*)d_in[4];
    const float* wv = (const float*)d_in[5];
    const float* bv = (const float*)d_in[6];
    const float* wo = (const float*)d_in[7];
    const float* bo = (const float*)d_in[8];
    float* out = (float*)d_out;

    const int qkv_smem   = 128 * 132 * 4;        // 67584 (pipeline 61440, staging 67584)
    const int oproj_smem = 3 * 2 * TSZB;         // 61440
    const int attn_smem  = 6 * KVSTG;            // 55296
    cudaFuncSetAttribute(qkv_gemm,    cudaFuncAttributeMaxDynamicSharedMemorySize, qkv_smem);
    cudaFuncSetAttribute(oproj_gemm,  cudaFuncAttributeMaxDynamicSharedMemorySize, oproj_smem);
    cudaFuncSetAttribute(attn_kernel, cudaFuncAttributeMaxDynamicSharedMemorySize, attn_smem);

    prep_pack<<<512 + 1728 + 512, 256>>>(x, wq, wk, wv, wo);
    qkv_gemm<<<dim3(8, 12, 16), 256, qkv_smem>>>(bq, bk, bv);
    attn_kernel<<<dim3(8, NH_, B_), 128, attn_smem>>>();
    oproj_gemm<<<dim3(8, 2, 16), 256, oproj_smem>>>(x, bo, out);
}

// round 14
// speedup vs baseline: 1.0228x; 1.0228x over previous
#include <cuda_runtime.h>
#include <cuda_bf16.h>
#include <cstdint>

#define B_    16
#define FIN_  256
#define NTOK_ 1024
#define NH_   8
#define FH_   64
#define CIN_  258
#define CPAD_ 288
#define COUT_ 512

typedef __nv_bfloat16 bf16;

// ---------------------------------------------------------------------------
__device__ bf16 g_t[B_ * NTOK_ * CPAD_];          // [b][n][c] padded to 288
__device__ bf16 g_w[3 * COUT_ * CPAD_];           // packed qkv weights
__device__ bf16 g_wo[FIN_ * COUT_];               // wo
__device__ bf16 g_q[B_ * NH_ * NTOK_ * FH_];      // [b][h][n][d]
__device__ bf16 g_k[B_ * NH_ * NTOK_ * FH_];      // [b][h][n][d]
__device__ bf16 g_v[B_ * NH_ * FH_ * NTOK_];      // [b][h][d][n]
__device__ bf16 g_o[B_ * NTOK_ * COUT_];          // [b][n][h*64+d]

// ---------------------------------------------------------------------------
__device__ __forceinline__ uint32_t smem_u32(const void* p) {
    uint32_t a;
    asm("{ .reg .u64 t; cvta.to.shared.u64 t, %1; cvt.u32.u64 %0, t; }" : "=r"(a) : "l"(p));
    return a;
}
__device__ __forceinline__ void cp16(uint32_t sdst, const void* gsrc) {
    asm volatile("cp.async.cg.shared.global [%0], [%1], 16;" :: "r"(sdst), "l"(gsrc));
}
#define CP_COMMIT() asm volatile("cp.async.commit_group;" ::: "memory")
#define CP_WAIT(n)  asm volatile("cp.async.wait_group %0;" :: "n"(n) : "memory")

__device__ __forceinline__ uint32_t pack2(float lo, float hi) {
    uint32_t r;
    asm("cvt.rn.bf16x2.f32 %0, %1, %2;" : "=r"(r) : "f"(hi), "f"(lo));
    return r;
}
__device__ __forceinline__ uint32_t ex2_bf16x2(uint32_t a) {
    uint32_t r;
    asm("ex2.approx.ftz.bf16x2 %0, %1;" : "=r"(r) : "r"(a));
    return r;
}
__device__ __forceinline__ void ldsm4(uint32_t r[4], uint32_t addr) {
    asm volatile("ldmatrix.sync.aligned.m8n8.x4.shared.b16 {%0,%1,%2,%3}, [%4];"
        : "=r"(r[0]), "=r"(r[1]), "=r"(r[2]), "=r"(r[3]) : "r"(addr));
}
__device__ __forceinline__ void mma16(float c[4], const uint32_t a[4], uint32_t b0, uint32_t b1) {
    asm volatile(
        "mma.sync.aligned.m16n8k16.row.col.f32.bf16.bf16.f32 "
        "{%0,%1,%2,%3}, {%4,%5,%6,%7}, {%8,%9}, {%0,%1,%2,%3};"
        : "+f"(c[0]), "+f"(c[1]), "+f"(c[2]), "+f"(c[3])
        : "r"(a[0]), "r"(a[1]), "r"(a[2]), "r"(a[3]), "r"(b0), "r"(b1));
}

// ---------------------------------------------------------------------------
// Kernel 0 (fused): prep t_T, pack qkv weights, pack wo.
__global__ __launch_bounds__(256) void prep_pack(
    const float* __restrict__ x,
    const float* __restrict__ wq, const float* __restrict__ wk, const float* __restrict__ wv,
    const float* __restrict__ wo)
{
    const int blk = blockIdx.x;
    if (blk < 512) {
        __shared__ float tile[32][33];
        const int nt = blk & 31, b = blk >> 5;
        const int tx = threadIdx.x & 31, ty = threadIdx.x >> 5;
        const int n0 = nt * 32;
        for (int c0 = 0; c0 < CPAD_; c0 += 32) {
            for (int ci = ty; ci < 32; ci += 8) {
                const int c = c0 + ci, n = n0 + tx;
                float v = 0.f;
                if (c < FIN_)           v = x[((size_t)b * FIN_ + c) * NTOK_ + n];
                else if (c == FIN_)     v = -1.f + (2.f / 31.f) * (float)(n >> 5);
                else if (c == FIN_ + 1) v = -1.f + (2.f / 31.f) * (float)(n & 31);
                tile[ci][tx] = v;
            }
            __syncthreads();
            for (int ni = ty; ni < 32; ni += 8)
                g_t[((size_t)b * NTOK_ + n0 + ni) * CPAD_ + c0 + tx] =
                    __float2bfloat16_rn(tile[tx][ni]);
            __syncthreads();
        }
    } else if (blk < 512 + 1728) {
        const int i = (blk - 512) * 256 + threadIdx.x;
        const int r = i / CPAD_, c = i - r * CPAD_;
        const int sel = r >> 9, o = r & 511;
        const float* w = (sel == 0) ? wq : ((sel == 1) ? wk : wv);
        g_w[i] = __float2bfloat16_rn((c < CIN_) ? w[o * CIN_ + c] : 0.f);
    } else {
        const int i = (blk - 512 - 1728) * 256 + threadIdx.x;
        g_wo[i] = __float2bfloat16_rn(wo[i]);
    }
}

// ---------------------------------------------------------------------------
// GEMM: CTA 128x128, 8 warps (4m x 2n), K-chunks 32 (2 k16 steps),
// 3-stage cp.async pipeline, one __syncthreads per chunk, ldmatrix fragments.
#define TSZB (128 * 80)
__global__ __launch_bounds__(256, 2) void qkv_gemm(
    const float* __restrict__ bq, const float* __restrict__ bk, const float* __restrict__ bv)
{
    extern __shared__ uint32_t sm[];
    const uint32_t sb = smem_u32(sm);

    const int tid = threadIdx.x;
    const int warp = tid >> 5, lane = tid & 31;
    const int g = lane >> 2, t4 = lane & 3;
    const int wm = warp & 3, wn = warp >> 2;
    const int nt = blockIdx.x, mt = blockIdx.y, b = blockIdx.z;
    const int sel = mt >> 2;
    const int o0 = (mt & 3) * 128;
    const int n0 = nt * 128;
    const bf16* wsrc = g_w + (size_t)(sel * COUT_ + o0) * CPAD_;
    const bf16* bsrc = g_t + ((size_t)b * NTOK_ + n0) * CPAD_;
    const float* bias = (sel == 0) ? bq : ((sel == 1) ? bk : bv);

    const uint32_t aoff = (uint32_t)((wm * 32 + (lane & 15)) * 80 + (lane >> 4) * 16);
    const uint32_t boff = (uint32_t)((wn * 64 + (lane >> 4) * 8 + (lane & 7)) * 80
                                     + ((lane >> 3) & 1) * 16);

    auto loadAB = [&](int kc, int st) {
        const uint32_t ab = sb + (uint32_t)(st * 2 * TSZB);
        const uint32_t bb = ab + TSZB;
        #pragma unroll
        for (int it = 0; it < 2; it++) {
            const int i = tid + it * 256;
            const int r = i >> 2, c4 = i & 3;
            cp16(ab + (uint32_t)(r * 80 + c4 * 16), wsrc + (size_t)r * CPAD_ + kc * 32 + c4 * 8);
            cp16(bb + (uint32_t)(r * 80 + c4 * 16), bsrc + (size_t)r * CPAD_ + kc * 32 + c4 * 8);
        }
    };

    float c[2][8][4];
    #pragma unroll
    for (int mi = 0; mi < 2; mi++)
        #pragma unroll
        for (int nf = 0; nf < 8; nf++)
            #pragma unroll
            for (int q = 0; q < 4; q++) c[mi][nf][q] = 0.f;

    loadAB(0, 0); CP_COMMIT();
    loadAB(1, 1); CP_COMMIT();

    const int NK = CPAD_ / 32;  // 9
    for (int kc = 0; kc < NK; kc++) {
        if (kc + 1 < NK) CP_WAIT(1); else CP_WAIT(0);
        __syncthreads();
        if (kc + 2 < NK) { loadAB(kc + 2, (kc + 2) % 3); CP_COMMIT(); }
        const uint32_t Ab = sb + (uint32_t)((kc % 3) * 2 * TSZB);
        const uint32_t Bb = Ab + TSZB;
        #pragma unroll
        for (int s = 0; s < 2; s++) {
            uint32_t a[2][4];
            ldsm4(a[0], Ab + aoff + s * 32);
            ldsm4(a[1], Ab + aoff + 16 * 80 + s * 32);
            #pragma unroll
            for (int nfp = 0; nfp < 4; nfp++) {
                uint32_t bb4[4];
                ldsm4(bb4, Bb + boff + nfp * 16 * 80 + s * 32);
                mma16(c[0][nfp * 2],     a[0], bb4[0], bb4[1]);
                mma16(c[1][nfp * 2],     a[1], bb4[0], bb4[1]);
                mma16(c[0][nfp * 2 + 1], a[0], bb4[2], bb4[3]);
                mma16(c[1][nfp * 2 + 1], a[1], bb4[2], bb4[3]);
            }
        }
    }
    __syncthreads();

    float* Cs = (float*)sm;   // staging reuse: 128*132*4 = 67584
    if (sel < 2) {
        #pragma unroll
        for (int mi = 0; mi < 2; mi++) {
            const int m0 = wm * 32 + mi * 16;
            const float bv0 = bias[o0 + m0 + g];
            const float bv1 = bias[o0 + m0 + g + 8];
            #pragma unroll
            for (int nf = 0; nf < 8; nf++) {
                const int nn = wn * 64 + nf * 8 + t4 * 2;
                Cs[(nn)     * 132 + m0 + g]     = c[mi][nf][0] + bv0;
                Cs[(nn + 1) * 132 + m0 + g]     = c[mi][nf][1] + bv0;
                Cs[(nn)     * 132 + m0 + g + 8] = c[mi][nf][2] + bv1;
                Cs[(nn + 1) * 132 + m0 + g + 8] = c[mi][nf][3] + bv1;
            }
        }
        __syncthreads();
        bf16* dstbase = (sel == 0) ? g_q : g_k;
        #pragma unroll
        for (int it = 0; it < 16; it++) {
            const int i = tid + it * 256;
            const int nl = i >> 5, m4 = i & 31;
            const float4 cv = *(const float4*)&Cs[nl * 132 + m4 * 4];
            const int o = o0 + m4 * 4;
            const int h = o >> 6, d = o & 63;
            uint2 pk = make_uint2(pack2(cv.x, cv.y), pack2(cv.z, cv.w));
            *(uint2*)&dstbase[(((size_t)b * NH_ + h) * NTOK_ + n0 + nl) * FH_ + d] = pk;
        }
    } else {
        #pragma unroll
        for (int mi = 0; mi < 2; mi++) {
            #pragma unroll
            for (int half = 0; half < 2; half++) {
                const int m = wm * 32 + mi * 16 + g + half * 8;
                const int o = o0 + m;
                const int h = o >> 6, d = o & 63;
                const float bval = bias[o];
                bf16* dst = g_v + (((size_t)b * NH_ + h) * FH_ + d) * NTOK_ + n0;
                #pragma unroll
                for (int nf = 0; nf < 8; nf++) {
                    const int nn = wn * 64 + nf * 8 + t4 * 2;
                    *(uint32_t*)&dst[nn] = pack2(c[mi][nf][half * 2] + bval,
                                                 c[mi][nf][half * 2 + 1] + bval);
                }
            }
        }
    }
}

// ---------------------------------------------------------------------------
// Kernel 2: attention. 128 threads, 4 warps, warp = 32 q rows (2 m-tiles),
// chunk processed in two 32-key halves to cap register peak (~170) so
// 3 CTAs/SM fit. Each K/V ldmatrix still feeds 4 MMAs (halved LDS traffic).
#define KVSTG 9216     // bytes per K or V stage
__global__ __launch_bounds__(128, 3) void attn_kernel() {
    extern __shared__ uint32_t sm[];
    const uint32_t sb = smem_u32(sm);
    const uint32_t KsB = sb, VsB = sb + 3 * KVSTG;

    const int tid = threadIdx.x;
    const int warp = tid >> 5, lane = tid & 31;
    const int g = lane >> 2, t4 = lane & 3;
    const int m0 = warp * 32;          // 32 q rows per warp
    const int qt = blockIdx.x, h = blockIdx.y, b = blockIdx.z;
    const size_t hb = (size_t)(b * NH_ + h);
    const bf16* qsrc = g_q + hb * NTOK_ * FH_ + (size_t)qt * 128 * FH_;
    const bf16* ksrc = g_k + hb * NTOK_ * FH_;
    const bf16* vsrc = g_v + hb * FH_ * NTOK_;

    const uint32_t kvoff = (uint32_t)(((lane >> 4) * 8 + (lane & 7)) * 144
                                      + ((lane >> 3) & 1) * 16);

    // Q fragments: 2 m-tiles x 4 k16 steps
    uint32_t qf[2][4][4];
    #pragma unroll
    for (int mi = 0; mi < 2; mi++) {
        const uint32_t* q0 = (const uint32_t*)(qsrc + (size_t)(m0 + mi * 16 + g) * FH_);
        const uint32_t* q1 = (const uint32_t*)(qsrc + (size_t)(m0 + mi * 16 + g + 8) * FH_);
        #pragma unroll
        for (int s = 0; s < 4; s++) {
            qf[mi][s][0] = q0[s * 8 + t4];
            qf[mi][s][1] = q1[s * 8 + t4];
            qf[mi][s][2] = q0[s * 8 + t4 + 4];
            qf[mi][s][3] = q1[s * 8 + t4 + 4];
        }
    }

    auto loadKV = [&](int ck, int st) {
        const int c0 = ck * 64;
        #pragma unroll
        for (int it = 0; it < 4; it++) {
            const int i = tid + it * 128;
            const int r = i >> 3, c8 = i & 7;
            cp16(KsB + (uint32_t)(st * KVSTG + r * 144 + c8 * 16),
                 ksrc + (size_t)(c0 + r) * FH_ + c8 * 8);
            cp16(VsB + (uint32_t)(st * KVSTG + r * 144 + c8 * 16),
                 vsrc + (size_t)r * NTOK_ + c0 + c8 * 8);
        }
    };

    float oacc[2][8][4];
    #pragma unroll
    for (int mi = 0; mi < 2; mi++)
        #pragma unroll
        for (int nf = 0; nf < 8; nf++)
            #pragma unroll
            for (int q = 0; q < 4; q++) oacc[mi][nf][q] = 0.f;
    float lsum[2][2] = {{0.f, 0.f}, {0.f, 0.f}};

    loadKV(0, 0); CP_COMMIT();
    loadKV(1, 1); CP_COMMIT();

    const float SC = 0.125f * 1.4426950408889634f;   // 1/sqrt(64) * log2(e)

    for (int ck = 0; ck < 16; ck++) {
        if (ck + 1 < 16) CP_WAIT(1); else CP_WAIT(0);
        __syncthreads();
        if (ck + 2 < 16) { loadKV(ck + 2, (ck + 2) % 3); CP_COMMIT(); }
        const uint32_t Kb = KsB + (uint32_t)((ck % 3) * KVSTG);
        const uint32_t Vb = VsB + (uint32_t)((ck % 3) * KVSTG);

        // Process chunk in two 32-key halves to cap the live register set.
        #pragma unroll
        for (int half = 0; half < 2; half++) {
            // S = Q K^T for keys [half*32, half*32+32)
            float sc[2][4][4];
            #pragma unroll
            for (int mi = 0; mi < 2; mi++)
                #pragma unroll
                for (int nf = 0; nf < 4; nf++)
                    #pragma unroll
                    for (int q = 0; q < 4; q++) sc[mi][nf][q] = 0.f;
            #pragma unroll
            for (int s = 0; s < 4; s++) {
                #pragma unroll
                for (int nfp = 0; nfp < 2; nfp++) {
                    uint32_t bb4[4];
                    ldsm4(bb4, Kb + kvoff + (half * 2 + nfp) * 16 * 144 + s * 32);
                    mma16(sc[0][nfp * 2],     qf[0][s], bb4[0], bb4[1]);
                    mma16(sc[0][nfp * 2 + 1], qf[0][s], bb4[2], bb4[3]);
                    mma16(sc[1][nfp * 2],     qf[1][s], bb4[0], bb4[1]);
                    mma16(sc[1][nfp * 2 + 1], qf[1][s], bb4[2], bb4[3]);
                }
            }

            // P = exp2(S*SC) bf16x2, register-resident (A-fragment layout)
            uint32_t pb[2][4][2];
            #pragma unroll
            for (int mi = 0; mi < 2; mi++)
                #pragma unroll
                for (int nf = 0; nf < 4; nf++) {
                    pb[mi][nf][0] = ex2_bf16x2(pack2(sc[mi][nf][0] * SC, sc[mi][nf][1] * SC));
                    pb[mi][nf][1] = ex2_bf16x2(pack2(sc[mi][nf][2] * SC, sc[mi][nf][3] * SC));
                }

            // O += P_half V_half^T : contraction k16 steps sg = half*2 + s2
            #pragma unroll
            for (int s2 = 0; s2 < 2; s2++) {
                const int sg = half * 2 + s2;
                const uint32_t pa0[4] = { pb[0][2 * s2][0], pb[0][2 * s2][1],
                                          pb[0][2 * s2 + 1][0], pb[0][2 * s2 + 1][1] };
                const uint32_t pa1[4] = { pb[1][2 * s2][0], pb[1][2 * s2][1],
                                          pb[1][2 * s2 + 1][0], pb[1][2 * s2 + 1][1] };
                #pragma unroll
                for (int nfp = 0; nfp < 4; nfp++) {
                    uint32_t bb4[4];
                    ldsm4(bb4, Vb + kvoff + nfp * 16 * 144 + sg * 32);
                    mma16(oacc[0][nfp * 2],     pa0, bb4[0], bb4[1]);
                    mma16(oacc[0][nfp * 2 + 1], pa0, bb4[2], bb4[3]);
                    mma16(oacc[1][nfp * 2],     pa1, bb4[0], bb4[1]);
                    mma16(oacc[1][nfp * 2 + 1], pa1, bb4[2], bb4[3]);
                }
            }

            // Row sums (overlap in-flight O-MMAs)
            #pragma unroll
            for (int mi = 0; mi < 2; mi++) {
                float s0 = 0.f, s1 = 0.f;
                #pragma unroll
                for (int nf = 0; nf < 4; nf++) {
                    const float2 f0 = __bfloat1622float2(*(__nv_bfloat162*)&pb[mi][nf][0]);
                    const float2 f1 = __bfloat1622float2(*(__nv_bfloat162*)&pb[mi][nf][1]);
                    s0 += f0.x + f0.y;
                    s1 += f1.x + f1.y;
                }
                s0 += __shfl_xor_sync(0xffffffffu, s0, 1);
                s0 += __shfl_xor_sync(0xffffffffu, s0, 2);
                s1 += __shfl_xor_sync(0xffffffffu, s1, 1);
                s1 += __shfl_xor_sync(0xffffffffu, s1, 2);
                lsum[mi][0] += s0;
                lsum[mi][1] += s1;
            }
        }
    }

    // normalize + write g_o[b][n][h*64+d] (bf16 pairs)
    #pragma unroll
    for (int mi = 0; mi < 2; mi++) {
        const float inv0 = 1.f / lsum[mi][0], inv1 = 1.f / lsum[mi][1];
        bf16* d0 = g_o + ((size_t)b * NTOK_ + qt * 128 + m0 + mi * 16 + g) * COUT_ + h * FH_;
        bf16* d1 = d0 + 8 * COUT_;
        #pragma unroll
        for (int nf = 0; nf < 8; nf++) {
            const int dd = nf * 8 + t4 * 2;
            *(uint32_t*)&d0[dd] = pack2(oacc[mi][nf][0] * inv0, oacc[mi][nf][1] * inv0);
            *(uint32_t*)&d1[dd] = pack2(oacc[mi][nf][2] * inv1, oacc[mi][nf][3] * inv1);
        }
    }
}

// ---------------------------------------------------------------------------
// Kernel 3: output projection + bias + residual, 3-stage pipeline.
__global__ __launch_bounds__(256, 2) void oproj_gemm(
    const float* __restrict__ x, const float* __restrict__ bo, float* __restrict__ out)
{
    extern __shared__ uint32_t sm[];
    const uint32_t sb = smem_u32(sm);

    const int tid = threadIdx.x;
    const int warp = tid >> 5, lane = tid & 31;
    const int g = lane >> 2, t4 = lane & 3;
    const int wm = warp & 3, wn = warp >> 2;
    const int nt = blockIdx.x, mt = blockIdx.y, b = blockIdx.z;
    const int o0 = mt * 128, n0 = nt * 128;
    const bf16* asrc = g_wo + (size_t)o0 * COUT_;
    const bf16* bsrc = g_o + ((size_t)b * NTOK_ + n0) * COUT_;

    const uint32_t aoff = (uint32_t)((wm * 32 + (lane & 15)) * 80 + (lane >> 4) * 16);
    const uint32_t boff = (uint32_t)((wn * 64 + (lane >> 4) * 8 + (lane & 7)) * 80
                                     + ((lane >> 3) & 1) * 16);

    auto loadAB = [&](int kc, int st) {
        const uint32_t ab = sb + (uint32_t)(st * 2 * TSZB);
        const uint32_t bb = ab + TSZB;
        #pragma unroll
        for (int it = 0; it < 2; it++) {
            const int i = tid + it * 256;
            const int r = i >> 2, c4 = i & 3;
            cp16(ab + (uint32_t)(r * 80 + c4 * 16), asrc + (size_t)r * COUT_ + kc * 32 + c4 * 8);
            cp16(bb + (uint32_t)(r * 80 + c4 * 16), bsrc + (size_t)r * COUT_ + kc * 32 + c4 * 8);
        }
    };

    float c[2][8][4];
    #pragma unroll
    for (int mi = 0; mi < 2; mi++)
        #pragma unroll
        for (int nf = 0; nf < 8; nf++)
            #pragma unroll
            for (int q = 0; q < 4; q++) c[mi][nf][q] = 0.f;

    loadAB(0, 0); CP_COMMIT();
    loadAB(1, 1); CP_COMMIT();

    const int NK = 16;
    for (int kc = 0; kc < NK; kc++) {
        if (kc + 1 < NK) CP_WAIT(1); else CP_WAIT(0);
        __syncthreads();
        if (kc + 2 < NK) { loadAB(kc + 2, (kc + 2) % 3); CP_COMMIT(); }
        const uint32_t Ab = sb + (uint32_t)((kc % 3) * 2 * TSZB);
        const uint32_t Bb = Ab + TSZB;
        #pragma unroll
        for (int s = 0; s < 2; s++) {
            uint32_t a[2][4];
            ldsm4(a[0], Ab + aoff + s * 32);
            ldsm4(a[1], Ab + aoff + 16 * 80 + s * 32);
            #pragma unroll
            for (int nfp = 0; nfp < 4; nfp++) {
                uint32_t bb4[4];
                ldsm4(bb4, Bb + boff + nfp * 16 * 80 + s * 32);
                mma16(c[0][nfp * 2],     a[0], bb4[0], bb4[1]);
                mma16(c[1][nfp * 2],     a[1], bb4[0], bb4[1]);
                mma16(c[0][nfp * 2 + 1], a[0], bb4[2], bb4[3]);
                mma16(c[1][nfp * 2 + 1], a[1], bb4[2], bb4[3]);
            }
        }
    }

    #pragma unroll
    for (int mi = 0; mi < 2; mi++) {
        #pragma unroll
        for (int half = 0; half < 2; half++) {
            const int m = o0 + wm * 32 + mi * 16 + g + half * 8;
            const float bval = bo[m];
            const float* xr = x + ((size_t)b * FIN_ + m) * NTOK_ + n0;
            float* outr = out + ((size_t)b * FIN_ + m) * NTOK_ + n0;
            #pragma unroll
            for (int nf = 0; nf < 8; nf++) {
                const int nn = wn * 64 + nf * 8 + t4 * 2;
                const float2 xv = *(const float2*)&xr[nn];
                *(float2*)&outr[nn] = make_float2(xv.x + bval + c[mi][nf][half * 2],
                                                  xv.y + bval + c[mi][nf][half * 2 + 1]);
            }
        }
    }
}

// ---------------------------------------------------------------------------
extern "C" void kernel_launch(void* const* d_in, const int* in_sizes, int n_in,
                              void* d_out, int out_size)
{
    const float* x  = (const float*)d_in[0];
    const float* wq = (const float*)d_in[1];
    const float* bq = (const float*)d_in[2];
    const float* wk = (const float*)d_in[3];
    const float* bk = (const float*)d_in[4];
    const float* wv = (const float*)d_in[5];
    const float* bv = (const float*)d_in[6];
    const float* wo = (const float*)d_in[7];
    const float* bo = (const float*)d_in[8];
    float* out = (float*)d_out;

    const int qkv_smem   = 128 * 132 * 4;        // 67584 (pipeline 61440, staging 67584)
    const int oproj_smem = 3 * 2 * TSZB;         // 61440
    const int attn_smem  = 6 * KVSTG;            // 55296
    cudaFuncSetAttribute(qkv_gemm,    cudaFuncAttributeMaxDynamicSharedMemorySize, qkv_smem);
    cudaFuncSetAttribute(oproj_gemm,  cudaFuncAttributeMaxDynamicSharedMemorySize, oproj_smem);
    cudaFuncSetAttribute(attn_kernel, cudaFuncAttributeMaxDynamicSharedMemorySize, attn_smem);

    prep_pack<<<512 + 1728 + 512, 256>>>(x, wq, wk, wv, wo);
    qkv_gemm<<<dim3(8, 12, 16), 256, qkv_smem>>>(bq, bk, bv);
    attn_kernel<<<dim3(8, NH_, B_), 128, attn_smem>>>();
    oproj_gemm<<<dim3(8, 2, 16), 256, oproj_smem>>>(x, bo, out);
}

// round 15
// speedup vs baseline: 1.0568x; 1.0332x over previous
#include <cuda_runtime.h>
#include <cuda_bf16.h>
#include <cstdint>

#define B_    16
#define FIN_  256
#define NTOK_ 1024
#define NH_   8
#define FH_   64
#define CIN_  258
#define CPAD_ 256          // main GEMM K; pos channels handled in epilogue
#define COUT_ 512

typedef __nv_bfloat16 bf16;

// ---------------------------------------------------------------------------
__device__ bf16 g_t[B_ * NTOK_ * CPAD_];          // [b][n][c], c<256 (x only)
__device__ bf16 g_w[3 * COUT_ * CPAD_];           // packed qkv weights, first 256 cols
__device__ bf16 g_wo[FIN_ * COUT_];               // wo
__device__ bf16 g_q[B_ * NH_ * NTOK_ * FH_];      // [b][h][n][d]
__device__ bf16 g_k[B_ * NH_ * NTOK_ * FH_];      // [b][h][n][d]
__device__ bf16 g_v[B_ * NH_ * FH_ * NTOK_];      // [b][h][d][n]
__device__ bf16 g_o[B_ * NTOK_ * COUT_];          // [b][n][h*64+d]

// ---------------------------------------------------------------------------
__device__ __forceinline__ uint32_t smem_u32(const void* p) {
    uint32_t a;
    asm("{ .reg .u64 t; cvta.to.shared.u64 t, %1; cvt.u32.u64 %0, t; }" : "=r"(a) : "l"(p));
    return a;
}
__device__ __forceinline__ void cp16(uint32_t sdst, const void* gsrc) {
    asm volatile("cp.async.cg.shared.global [%0], [%1], 16;" :: "r"(sdst), "l"(gsrc));
}
#define CP_COMMIT() asm volatile("cp.async.commit_group;" ::: "memory")
#define CP_WAIT(n)  asm volatile("cp.async.wait_group %0;" :: "n"(n) : "memory")

__device__ __forceinline__ uint32_t pack2(float lo, float hi) {
    uint32_t r;
    asm("cvt.rn.bf16x2.f32 %0, %1, %2;" : "=r"(r) : "f"(hi), "f"(lo));
    return r;
}
__device__ __forceinline__ uint32_t ex2_bf16x2(uint32_t a) {
    uint32_t r;
    asm("ex2.approx.ftz.bf16x2 %0, %1;" : "=r"(r) : "r"(a));
    return r;
}
__device__ __forceinline__ void ldsm4(uint32_t r[4], uint32_t addr) {
    asm volatile("ldmatrix.sync.aligned.m8n8.x4.shared.b16 {%0,%1,%2,%3}, [%4];"
        : "=r"(r[0]), "=r"(r[1]), "=r"(r[2]), "=r"(r[3]) : "r"(addr));
}
__device__ __forceinline__ void mma16(float c[4], const uint32_t a[4], uint32_t b0, uint32_t b1) {
    asm volatile(
        "mma.sync.aligned.m16n8k16.row.col.f32.bf16.bf16.f32 "
        "{%0,%1,%2,%3}, {%4,%5,%6,%7}, {%8,%9}, {%0,%1,%2,%3};"
        : "+f"(c[0]), "+f"(c[1]), "+f"(c[2]), "+f"(c[3])
        : "r"(a[0]), "r"(a[1]), "r"(a[2]), "r"(a[3]), "r"(b0), "r"(b1));
}
__device__ __forceinline__ float gyf(int n) { return -1.f + (2.f / 31.f) * (float)(n >> 5); }
__device__ __forceinline__ float gxf(int n) { return -1.f + (2.f / 31.f) * (float)(n & 31); }

// ---------------------------------------------------------------------------
// Kernel 0 (fused): transpose x -> g_t (c<256 only), pack qkv weights, pack wo.
__global__ __launch_bounds__(256) void prep_pack(
    const float* __restrict__ x,
    const float* __restrict__ wq, const float* __restrict__ wk, const float* __restrict__ wv,
    const float* __restrict__ wo)
{
    const int blk = blockIdx.x;
    if (blk < 512) {
        __shared__ float tile[32][33];
        const int nt = blk & 31, b = blk >> 5;
        const int tx = threadIdx.x & 31, ty = threadIdx.x >> 5;
        const int n0 = nt * 32;
        for (int c0 = 0; c0 < FIN_; c0 += 32) {
            for (int ci = ty; ci < 32; ci += 8)
                tile[ci][tx] = x[((size_t)b * FIN_ + c0 + ci) * NTOK_ + n0 + tx];
            __syncthreads();
            for (int ni = ty; ni < 32; ni += 8)
                g_t[((size_t)b * NTOK_ + n0 + ni) * CPAD_ + c0 + tx] =
                    __float2bfloat16_rn(tile[tx][ni]);
            __syncthreads();
        }
    } else if (blk < 512 + 1536) {
        const int i = (blk - 512) * 256 + threadIdx.x;       // 3*512*256
        const int r = i >> 8, c = i & 255;
        const int sel = r >> 9, o = r & 511;
        const float* w = (sel == 0) ? wq : ((sel == 1) ? wk : wv);
        g_w[i] = __float2bfloat16_rn(w[o * CIN_ + c]);
    } else {
        const int i = (blk - 512 - 1536) * 256 + threadIdx.x; // 256*512
        g_wo[i] = __float2bfloat16_rn(wo[i]);
    }
}

// ---------------------------------------------------------------------------
// GEMM: CTA 128x128, 8 warps (4m x 2n), K=256 (8 chunks of 32), 3-stage
// cp.async pipeline, ldmatrix fragments. Pos channels added in epilogue (fp32).
#define TSZB (128 * 80)
__global__ __launch_bounds__(256, 2) void qkv_gemm(
    const float* __restrict__ wq, const float* __restrict__ bq,
    const float* __restrict__ wk, const float* __restrict__ bk,
    const float* __restrict__ wv, const float* __restrict__ bv)
{
    extern __shared__ uint32_t sm[];
    const uint32_t sb = smem_u32(sm);

    const int tid = threadIdx.x;
    const int warp = tid >> 5, lane = tid & 31;
    const int g = lane >> 2, t4 = lane & 3;
    const int wm = warp & 3, wn = warp >> 2;
    const int nt = blockIdx.x, mt = blockIdx.y, b = blockIdx.z;
    const int sel = mt >> 2;
    const int o0 = (mt & 3) * 128;
    const int n0 = nt * 128;
    const bf16* wsrc = g_w + (size_t)(sel * COUT_ + o0) * CPAD_;
    const bf16* bsrc = g_t + ((size_t)b * NTOK_ + n0) * CPAD_;
    const float* wfull = (sel == 0) ? wq : ((sel == 1) ? wk : wv);
    const float* bias  = (sel == 0) ? bq : ((sel == 1) ? bk : bv);

    const uint32_t aoff = (uint32_t)((wm * 32 + (lane & 15)) * 80 + (lane >> 4) * 16);
    const uint32_t boff = (uint32_t)((wn * 64 + (lane >> 4) * 8 + (lane & 7)) * 80
                                     + ((lane >> 3) & 1) * 16);

    auto loadAB = [&](int kc, int st) {
        const uint32_t ab = sb + (uint32_t)(st * 2 * TSZB);
        const uint32_t bb = ab + TSZB;
        #pragma unroll
        for (int it = 0; it < 2; it++) {
            const int i = tid + it * 256;
            const int r = i >> 2, c4 = i & 3;
            cp16(ab + (uint32_t)(r * 80 + c4 * 16), wsrc + (size_t)r * CPAD_ + kc * 32 + c4 * 8);
            cp16(bb + (uint32_t)(r * 80 + c4 * 16), bsrc + (size_t)r * CPAD_ + kc * 32 + c4 * 8);
        }
    };

    float c[2][8][4];
    #pragma unroll
    for (int mi = 0; mi < 2; mi++)
        #pragma unroll
        for (int nf = 0; nf < 8; nf++)
            #pragma unroll
            for (int q = 0; q < 4; q++) c[mi][nf][q] = 0.f;

    loadAB(0, 0); CP_COMMIT();
    loadAB(1, 1); CP_COMMIT();

    const int NK = CPAD_ / 32;  // 8
    for (int kc = 0; kc < NK; kc++) {
        if (kc + 1 < NK) CP_WAIT(1); else CP_WAIT(0);
        __syncthreads();
        if (kc + 2 < NK) { loadAB(kc + 2, (kc + 2) % 3); CP_COMMIT(); }
        const uint32_t Ab = sb + (uint32_t)((kc % 3) * 2 * TSZB);
        const uint32_t Bb = Ab + TSZB;
        #pragma unroll
        for (int s = 0; s < 2; s++) {
            uint32_t a[2][4];
            ldsm4(a[0], Ab + aoff + s * 32);
            ldsm4(a[1], Ab + aoff + 16 * 80 + s * 32);
            #pragma unroll
            for (int nfp = 0; nfp < 4; nfp++) {
                uint32_t bb4[4];
                ldsm4(bb4, Bb + boff + nfp * 16 * 80 + s * 32);
                mma16(c[0][nfp * 2],     a[0], bb4[0], bb4[1]);
                mma16(c[1][nfp * 2],     a[1], bb4[0], bb4[1]);
                mma16(c[0][nfp * 2 + 1], a[0], bb4[2], bb4[3]);
                mma16(c[1][nfp * 2 + 1], a[1], bb4[2], bb4[3]);
            }
        }
    }

    // Pos-channel rank-2 update (exact fp32): c += w[:,256]*gy(n) + w[:,257]*gx(n)
    #pragma unroll
    for (int mi = 0; mi < 2; mi++) {
        const int r0 = o0 + wm * 32 + mi * 16 + g;
        const float2 wp0 = *(const float2*)&wfull[(size_t)r0 * CIN_ + 256];
        const float2 wp1 = *(const float2*)&wfull[(size_t)(r0 + 8) * CIN_ + 256];
        #pragma unroll
        for (int nf = 0; nf < 8; nf++) {
            const int n = n0 + wn * 64 + nf * 8 + t4 * 2;
            const float gy0 = gyf(n),     gx0 = gxf(n);
            const float gy1 = gyf(n + 1), gx1 = gxf(n + 1);
            c[mi][nf][0] += wp0.x * gy0 + wp0.y * gx0;
            c[mi][nf][1] += wp0.x * gy1 + wp0.y * gx1;
            c[mi][nf][2] += wp1.x * gy0 + wp1.y * gx0;
            c[mi][nf][3] += wp1.x * gy1 + wp1.y * gx1;
        }
    }
    __syncthreads();

    float* Cs = (float*)sm;   // staging reuse: 128*132*4 = 67584
    if (sel < 2) {
        #pragma unroll
        for (int mi = 0; mi < 2; mi++) {
            const int m0 = wm * 32 + mi * 16;
            const float bv0 = bias[o0 + m0 + g];
            const float bv1 = bias[o0 + m0 + g + 8];
            #pragma unroll
            for (int nf = 0; nf < 8; nf++) {
                const int nn = wn * 64 + nf * 8 + t4 * 2;
                Cs[(nn)     * 132 + m0 + g]     = c[mi][nf][0] + bv0;
                Cs[(nn + 1) * 132 + m0 + g]     = c[mi][nf][1] + bv0;
                Cs[(nn)     * 132 + m0 + g + 8] = c[mi][nf][2] + bv1;
                Cs[(nn + 1) * 132 + m0 + g + 8] = c[mi][nf][3] + bv1;
            }
        }
        __syncthreads();
        bf16* dstbase = (sel == 0) ? g_q : g_k;
        #pragma unroll
        for (int it = 0; it < 16; it++) {
            const int i = tid + it * 256;
            const int nl = i >> 5, m4 = i & 31;
            const float4 cv = *(const float4*)&Cs[nl * 132 + m4 * 4];
            const int o = o0 + m4 * 4;
            const int h = o >> 6, d = o & 63;
            uint2 pk = make_uint2(pack2(cv.x, cv.y), pack2(cv.z, cv.w));
            *(uint2*)&dstbase[(((size_t)b * NH_ + h) * NTOK_ + n0 + nl) * FH_ + d] = pk;
        }
    } else {
        #pragma unroll
        for (int mi = 0; mi < 2; mi++) {
            #pragma unroll
            for (int half = 0; half < 2; half++) {
                const int m = wm * 32 + mi * 16 + g + half * 8;
                const int o = o0 + m;
                const int h = o >> 6, d = o & 63;
                const float bval = bias[o];
                bf16* dst = g_v + (((size_t)b * NH_ + h) * FH_ + d) * NTOK_ + n0;
                #pragma unroll
                for (int nf = 0; nf < 8; nf++) {
                    const int nn = wn * 64 + nf * 8 + t4 * 2;
                    *(uint32_t*)&dst[nn] = pack2(c[mi][nf][half * 2] + bval,
                                                 c[mi][nf][half * 2 + 1] + bval);
                }
            }
        }
    }
}

// ---------------------------------------------------------------------------
// Kernel 2: attention (R14 structure) + shuffle reductions hoisted out of loop.
#define KVSTG 9216
__global__ __launch_bounds__(128, 3) void attn_kernel() {
    extern __shared__ uint32_t sm[];
    const uint32_t sb = smem_u32(sm);
    const uint32_t KsB = sb, VsB = sb + 3 * KVSTG;

    const int tid = threadIdx.x;
    const int warp = tid >> 5, lane = tid & 31;
    const int g = lane >> 2, t4 = lane & 3;
    const int m0 = warp * 32;
    const int qt = blockIdx.x, h = blockIdx.y, b = blockIdx.z;
    const size_t hb = (size_t)(b * NH_ + h);
    const bf16* qsrc = g_q + hb * NTOK_ * FH_ + (size_t)qt * 128 * FH_;
    const bf16* ksrc = g_k + hb * NTOK_ * FH_;
    const bf16* vsrc = g_v + hb * FH_ * NTOK_;

    const uint32_t kvoff = (uint32_t)(((lane >> 4) * 8 + (lane & 7)) * 144
                                      + ((lane >> 3) & 1) * 16);

    uint32_t qf[2][4][4];
    #pragma unroll
    for (int mi = 0; mi < 2; mi++) {
        const uint32_t* q0 = (const uint32_t*)(qsrc + (size_t)(m0 + mi * 16 + g) * FH_);
        const uint32_t* q1 = (const uint32_t*)(qsrc + (size_t)(m0 + mi * 16 + g + 8) * FH_);
        #pragma unroll
        for (int s = 0; s < 4; s++) {
            qf[mi][s][0] = q0[s * 8 + t4];
            qf[mi][s][1] = q1[s * 8 + t4];
            qf[mi][s][2] = q0[s * 8 + t4 + 4];
            qf[mi][s][3] = q1[s * 8 + t4 + 4];
        }
    }

    auto loadKV = [&](int ck, int st) {
        const int c0 = ck * 64;
        #pragma unroll
        for (int it = 0; it < 4; it++) {
            const int i = tid + it * 128;
            const int r = i >> 3, c8 = i & 7;
            cp16(KsB + (uint32_t)(st * KVSTG + r * 144 + c8 * 16),
                 ksrc + (size_t)(c0 + r) * FH_ + c8 * 8);
            cp16(VsB + (uint32_t)(st * KVSTG + r * 144 + c8 * 16),
                 vsrc + (size_t)r * NTOK_ + c0 + c8 * 8);
        }
    };

    float oacc[2][8][4];
    #pragma unroll
    for (int mi = 0; mi < 2; mi++)
        #pragma unroll
        for (int nf = 0; nf < 8; nf++)
            #pragma unroll
            for (int q = 0; q < 4; q++) oacc[mi][nf][q] = 0.f;
    float lsum[2][2] = {{0.f, 0.f}, {0.f, 0.f}};   // raw per-lane partials

    loadKV(0, 0); CP_COMMIT();
    loadKV(1, 1); CP_COMMIT();

    const float SC = 0.125f * 1.4426950408889634f;

    for (int ck = 0; ck < 16; ck++) {
        if (ck + 1 < 16) CP_WAIT(1); else CP_WAIT(0);
        __syncthreads();
        if (ck + 2 < 16) { loadKV(ck + 2, (ck + 2) % 3); CP_COMMIT(); }
        const uint32_t Kb = KsB + (uint32_t)((ck % 3) * KVSTG);
        const uint32_t Vb = VsB + (uint32_t)((ck % 3) * KVSTG);

        #pragma unroll
        for (int half = 0; half < 2; half++) {
            float sc[2][4][4];
            #pragma unroll
            for (int mi = 0; mi < 2; mi++)
                #pragma unroll
                for (int nf = 0; nf < 4; nf++)
                    #pragma unroll
                    for (int q = 0; q < 4; q++) sc[mi][nf][q] = 0.f;
            #pragma unroll
            for (int s = 0; s < 4; s++) {
                #pragma unroll
                for (int nfp = 0; nfp < 2; nfp++) {
                    uint32_t bb4[4];
                    ldsm4(bb4, Kb + kvoff + (half * 2 + nfp) * 16 * 144 + s * 32);
                    mma16(sc[0][nfp * 2],     qf[0][s], bb4[0], bb4[1]);
                    mma16(sc[0][nfp * 2 + 1], qf[0][s], bb4[2], bb4[3]);
                    mma16(sc[1][nfp * 2],     qf[1][s], bb4[0], bb4[1]);
                    mma16(sc[1][nfp * 2 + 1], qf[1][s], bb4[2], bb4[3]);
                }
            }

            uint32_t pb[2][4][2];
            #pragma unroll
            for (int mi = 0; mi < 2; mi++)
                #pragma unroll
                for (int nf = 0; nf < 4; nf++) {
                    pb[mi][nf][0] = ex2_bf16x2(pack2(sc[mi][nf][0] * SC, sc[mi][nf][1] * SC));
                    pb[mi][nf][1] = ex2_bf16x2(pack2(sc[mi][nf][2] * SC, sc[mi][nf][3] * SC));
                }

            #pragma unroll
            for (int s2 = 0; s2 < 2; s2++) {
                const int sg = half * 2 + s2;
                const uint32_t pa0[4] = { pb[0][2 * s2][0], pb[0][2 * s2][1],
                                          pb[0][2 * s2 + 1][0], pb[0][2 * s2 + 1][1] };
                const uint32_t pa1[4] = { pb[1][2 * s2][0], pb[1][2 * s2][1],
                                          pb[1][2 * s2 + 1][0], pb[1][2 * s2 + 1][1] };
                #pragma unroll
                for (int nfp = 0; nfp < 4; nfp++) {
                    uint32_t bb4[4];
                    ldsm4(bb4, Vb + kvoff + nfp * 16 * 144 + sg * 32);
                    mma16(oacc[0][nfp * 2],     pa0, bb4[0], bb4[1]);
                    mma16(oacc[0][nfp * 2 + 1], pa0, bb4[2], bb4[3]);
                    mma16(oacc[1][nfp * 2],     pa1, bb4[0], bb4[1]);
                    mma16(oacc[1][nfp * 2 + 1], pa1, bb4[2], bb4[3]);
                }
            }

            // raw partial row sums only (shuffle reductions hoisted to the end)
            #pragma unroll
            for (int mi = 0; mi < 2; mi++) {
                #pragma unroll
                for (int nf = 0; nf < 4; nf++) {
                    const float2 f0 = __bfloat1622float2(*(__nv_bfloat162*)&pb[mi][nf][0]);
                    const float2 f1 = __bfloat1622float2(*(__nv_bfloat162*)&pb[mi][nf][1]);
                    lsum[mi][0] += f0.x + f0.y;
                    lsum[mi][1] += f1.x + f1.y;
                }
            }
        }
    }

    // final cross-lane reduction (once)
    #pragma unroll
    for (int mi = 0; mi < 2; mi++) {
        lsum[mi][0] += __shfl_xor_sync(0xffffffffu, lsum[mi][0], 1);
        lsum[mi][0] += __shfl_xor_sync(0xffffffffu, lsum[mi][0], 2);
        lsum[mi][1] += __shfl_xor_sync(0xffffffffu, lsum[mi][1], 1);
        lsum[mi][1] += __shfl_xor_sync(0xffffffffu, lsum[mi][1], 2);
    }

    #pragma unroll
    for (int mi = 0; mi < 2; mi++) {
        const float inv0 = 1.f / lsum[mi][0], inv1 = 1.f / lsum[mi][1];
        bf16* d0 = g_o + ((size_t)b * NTOK_ + qt * 128 + m0 + mi * 16 + g) * COUT_ + h * FH_;
        bf16* d1 = d0 + 8 * COUT_;
        #pragma unroll
        for (int nf = 0; nf < 8; nf++) {
            const int dd = nf * 8 + t4 * 2;
            *(uint32_t*)&d0[dd] = pack2(oacc[mi][nf][0] * inv0, oacc[mi][nf][1] * inv0);
            *(uint32_t*)&d1[dd] = pack2(oacc[mi][nf][2] * inv1, oacc[mi][nf][3] * inv1);
        }
    }
}

// ---------------------------------------------------------------------------
// Kernel 3: output projection + bias + residual, 3-stage pipeline.
__global__ __launch_bounds__(256, 2) void oproj_gemm(
    const float* __restrict__ x, const float* __restrict__ bo, float* __restrict__ out)
{
    extern __shared__ uint32_t sm[];
    const uint32_t sb = smem_u32(sm);

    const int tid = threadIdx.x;
    const int warp = tid >> 5, lane = tid & 31;
    const int g = lane >> 2, t4 = lane & 3;
    const int wm = warp & 3, wn = warp >> 2;
    const int nt = blockIdx.x, mt = blockIdx.y, b = blockIdx.z;
    const int o0 = mt * 128, n0 = nt * 128;
    const bf16* asrc = g_wo + (size_t)o0 * COUT_;
    const bf16* bsrc = g_o + ((size_t)b * NTOK_ + n0) * COUT_;

    const uint32_t aoff = (uint32_t)((wm * 32 + (lane & 15)) * 80 + (lane >> 4) * 16);
    const uint32_t boff = (uint32_t)((wn * 64 + (lane >> 4) * 8 + (lane & 7)) * 80
                                     + ((lane >> 3) & 1) * 16);

    auto loadAB = [&](int kc, int st) {
        const uint32_t ab = sb + (uint32_t)(st * 2 * TSZB);
        const uint32_t bb = ab + TSZB;
        #pragma unroll
        for (int it = 0; it < 2; it++) {
            const int i = tid + it * 256;
            const int r = i >> 2, c4 = i & 3;
            cp16(ab + (uint32_t)(r * 80 + c4 * 16), asrc + (size_t)r * COUT_ + kc * 32 + c4 * 8);
            cp16(bb + (uint32_t)(r * 80 + c4 * 16), bsrc + (size_t)r * COUT_ + kc * 32 + c4 * 8);
        }
    };

    float c[2][8][4];
    #pragma unroll
    for (int mi = 0; mi < 2; mi++)
        #pragma unroll
        for (int nf = 0; nf < 8; nf++)
            #pragma unroll
            for (int q = 0; q < 4; q++) c[mi][nf][q] = 0.f;

    loadAB(0, 0); CP_COMMIT();
    loadAB(1, 1); CP_COMMIT();

    const int NK = 16;
    for (int kc = 0; kc < NK; kc++) {
        if (kc + 1 < NK) CP_WAIT(1); else CP_WAIT(0);
        __syncthreads();
        if (kc + 2 < NK) { loadAB(kc + 2, (kc + 2) % 3); CP_COMMIT(); }
        const uint32_t Ab = sb + (uint32_t)((kc % 3) * 2 * TSZB);
        const uint32_t Bb = Ab + TSZB;
        #pragma unroll
        for (int s = 0; s < 2; s++) {
            uint32_t a[2][4];
            ldsm4(a[0], Ab + aoff + s * 32);
            ldsm4(a[1], Ab + aoff + 16 * 80 + s * 32);
            #pragma unroll
            for (int nfp = 0; nfp < 4; nfp++) {
                uint32_t bb4[4];
                ldsm4(bb4, Bb + boff + nfp * 16 * 80 + s * 32);
                mma16(c[0][nfp * 2],     a[0], bb4[0], bb4[1]);
                mma16(c[1][nfp * 2],     a[1], bb4[0], bb4[1]);
                mma16(c[0][nfp * 2 + 1], a[0], bb4[2], bb4[3]);
                mma16(c[1][nfp * 2 + 1], a[1], bb4[2], bb4[3]);
            }
        }
    }

    #pragma unroll
    for (int mi = 0; mi < 2; mi++) {
        #pragma unroll
        for (int half = 0; half < 2; half++) {
            const int m = o0 + wm * 32 + mi * 16 + g + half * 8;
            const float bval = bo[m];
            const float* xr = x + ((size_t)b * FIN_ + m) * NTOK_ + n0;
            float* outr = out + ((size_t)b * FIN_ + m) * NTOK_ + n0;
            #pragma unroll
            for (int nf = 0; nf < 8; nf++) {
                const int nn = wn * 64 + nf * 8 + t4 * 2;
                const float2 xv = *(const float2*)&xr[nn];
                *(float2*)&outr[nn] = make_float2(xv.x + bval + c[mi][nf][half * 2],
                                                  xv.y + bval + c[mi][nf][half * 2 + 1]);
            }
        }
    }
}

// ---------------------------------------------------------------------------
extern "C" void kernel_launch(void* const* d_in, const int* in_sizes, int n_in,
                              void* d_out, int out_size)
{
    const float* x  = (const float*)d_in[0];
    const float* wq = (const float*)d_in[1];
    const float* bq = (const float*)d_in[2];
    const float* wk = (const float*)d_in[3];
    const float* bk = (const float*)d_in[4];
    const float* wv = (const float*)d_in[5];
    const float* bv = (const float*)d_in[6];
    const float* wo = (const float*)d_in[7];
    const float* bo = (const float*)d_in[8];
    float* out = (float*)d_out;

    const int qkv_smem   = 128 * 132 * 4;        // 67584 (pipeline 61440, staging 67584)
    const int oproj_smem = 3 * 2 * TSZB;         // 61440
    const int attn_smem  = 6 * KVSTG;            // 55296
    cudaFuncSetAttribute(qkv_gemm,    cudaFuncAttributeMaxDynamicSharedMemorySize, qkv_smem);
    cudaFuncSetAttribute(oproj_gemm,  cudaFuncAttributeMaxDynamicSharedMemorySize, oproj_smem);
    cudaFuncSetAttribute(attn_kernel, cudaFuncAttributeMaxDynamicSharedMemorySize, attn_smem);

    prep_pack<<<512 + 1536 + 512, 256>>>(x, wq, wk, wv, wo);
    qkv_gemm<<<dim3(8, 12, 16), 256, qkv_smem>>>(wq, bq, wk, bk, wv, bv);
    attn_kernel<<<dim3(8, NH_, B_), 128, attn_smem>>>();
    oproj_gemm<<<dim3(8, 2, 16), 256, oproj_smem>>>(x, bo, out);
}

// round 16
// speedup vs baseline: 1.0953x; 1.0364x over previous
#include <cuda_runtime.h>
#include <cuda_bf16.h>
#include <cstdint>

#define B_    16
#define FIN_  256
#define NTOK_ 1024
#define NH_   8
#define FH_   64
#define CIN_  258
#define CPAD_ 256          // main GEMM K; pos channels handled in epilogue
#define COUT_ 512

typedef __nv_bfloat16 bf16;

// ---------------------------------------------------------------------------
__device__ bf16 g_t[B_ * NTOK_ * CPAD_];          // [b][n][c], c<256 (x only)
__device__ bf16 g_w[3 * COUT_ * CPAD_];           // packed qkv weights, first 256 cols
__device__ bf16 g_wo[FIN_ * COUT_];               // wo
__device__ bf16 g_q[B_ * NH_ * NTOK_ * FH_];      // [b][h][n][d]
__device__ bf16 g_k[B_ * NH_ * NTOK_ * FH_];      // [b][h][n][d]
__device__ bf16 g_v[B_ * NH_ * FH_ * NTOK_];      // [b][h][d][n]
__device__ bf16 g_o[B_ * NTOK_ * COUT_];          // [b][n][h*64+d]

// ---------------------------------------------------------------------------
__device__ __forceinline__ uint32_t smem_u32(const void* p) {
    uint32_t a;
    asm("{ .reg .u64 t; cvta.to.shared.u64 t, %1; cvt.u32.u64 %0, t; }" : "=r"(a) : "l"(p));
    return a;
}
__device__ __forceinline__ void cp16(uint32_t sdst, const void* gsrc) {
    asm volatile("cp.async.cg.shared.global [%0], [%1], 16;" :: "r"(sdst), "l"(gsrc));
}
#define CP_COMMIT() asm volatile("cp.async.commit_group;" ::: "memory")
#define CP_WAIT(n)  asm volatile("cp.async.wait_group %0;" :: "n"(n) : "memory")

__device__ __forceinline__ uint32_t pack2(float lo, float hi) {
    uint32_t r;
    asm("cvt.rn.bf16x2.f32 %0, %1, %2;" : "=r"(r) : "f"(hi), "f"(lo));
    return r;
}
__device__ __forceinline__ uint32_t ex2_bf16x2(uint32_t a) {
    uint32_t r;
    asm("ex2.approx.ftz.bf16x2 %0, %1;" : "=r"(r) : "r"(a));
    return r;
}
__device__ __forceinline__ void ldsm4(uint32_t r[4], uint32_t addr) {
    asm volatile("ldmatrix.sync.aligned.m8n8.x4.shared.b16 {%0,%1,%2,%3}, [%4];"
        : "=r"(r[0]), "=r"(r[1]), "=r"(r[2]), "=r"(r[3]) : "r"(addr));
}
__device__ __forceinline__ void mma16(float c[4], const uint32_t a[4], uint32_t b0, uint32_t b1) {
    asm volatile(
        "mma.sync.aligned.m16n8k16.row.col.f32.bf16.bf16.f32 "
        "{%0,%1,%2,%3}, {%4,%5,%6,%7}, {%8,%9}, {%0,%1,%2,%3};"
        : "+f"(c[0]), "+f"(c[1]), "+f"(c[2]), "+f"(c[3])
        : "r"(a[0]), "r"(a[1]), "r"(a[2]), "r"(a[3]), "r"(b0), "r"(b1));
}
__device__ __forceinline__ float gyf(int n) { return -1.f + (2.f / 31.f) * (float)(n >> 5); }
__device__ __forceinline__ float gxf(int n) { return -1.f + (2.f / 31.f) * (float)(n & 31); }

// ---------------------------------------------------------------------------
// Kernel 0 (fused): transpose x -> g_t (c<256 only), pack qkv weights, pack wo.
__global__ __launch_bounds__(256) void prep_pack(
    const float* __restrict__ x,
    const float* __restrict__ wq, const float* __restrict__ wk, const float* __restrict__ wv,
    const float* __restrict__ wo)
{
    const int blk = blockIdx.x;
    if (blk < 512) {
        __shared__ float tile[32][33];
        const int nt = blk & 31, b = blk >> 5;
        const int tx = threadIdx.x & 31, ty = threadIdx.x >> 5;
        const int n0 = nt * 32;
        for (int c0 = 0; c0 < FIN_; c0 += 32) {
            for (int ci = ty; ci < 32; ci += 8)
                tile[ci][tx] = x[((size_t)b * FIN_ + c0 + ci) * NTOK_ + n0 + tx];
            __syncthreads();
            for (int ni = ty; ni < 32; ni += 8)
                g_t[((size_t)b * NTOK_ + n0 + ni) * CPAD_ + c0 + tx] =
                    __float2bfloat16_rn(tile[tx][ni]);
            __syncthreads();
        }
    } else if (blk < 512 + 1536) {
        const int i = (blk - 512) * 256 + threadIdx.x;       // 3*512*256
        const int r = i >> 8, c = i & 255;
        const int sel = r >> 9, o = r & 511;
        const float* w = (sel == 0) ? wq : ((sel == 1) ? wk : wv);
        g_w[i] = __float2bfloat16_rn(w[o * CIN_ + c]);
    } else {
        const int i = (blk - 512 - 1536) * 256 + threadIdx.x; // 256*512
        g_wo[i] = __float2bfloat16_rn(wo[i]);
    }
}

// ---------------------------------------------------------------------------
// GEMM: CTA 128x128, 8 warps (4m x 2n), K-chunks 64 (4 k16 steps), pitch 144B,
// 3-stage cp.async pipeline, ONE barrier per 64-K chunk, ldmatrix fragments.
#define AT64  18432          // 128 rows x 144B
#define STG64 (2 * AT64)     // A + B per stage = 36864
__global__ __launch_bounds__(256, 2) void qkv_gemm(
    const float* __restrict__ wq, const float* __restrict__ bq,
    const float* __restrict__ wk, const float* __restrict__ bk,
    const float* __restrict__ wv, const float* __restrict__ bv)
{
    extern __shared__ uint32_t sm[];
    const uint32_t sb = smem_u32(sm);

    const int tid = threadIdx.x;
    const int warp = tid >> 5, lane = tid & 31;
    const int g = lane >> 2, t4 = lane & 3;
    const int wm = warp & 3, wn = warp >> 2;
    const int nt = blockIdx.x, mt = blockIdx.y, b = blockIdx.z;
    const int sel = mt >> 2;
    const int o0 = (mt & 3) * 128;
    const int n0 = nt * 128;
    const bf16* wsrc = g_w + (size_t)(sel * COUT_ + o0) * CPAD_;
    const bf16* bsrc = g_t + ((size_t)b * NTOK_ + n0) * CPAD_;
    const float* wfull = (sel == 0) ? wq : ((sel == 1) ? wk : wv);
    const float* bias  = (sel == 0) ? bq : ((sel == 1) ? bk : bv);

    const uint32_t aoff = (uint32_t)((wm * 32 + (lane & 15)) * 144 + (lane >> 4) * 16);
    const uint32_t boff = (uint32_t)((wn * 64 + (lane >> 4) * 8 + (lane & 7)) * 144
                                     + ((lane >> 3) & 1) * 16);

    auto loadAB = [&](int kc, int st) {
        const uint32_t ab = sb + (uint32_t)(st * STG64);
        const uint32_t bb = ab + AT64;
        #pragma unroll
        for (int it = 0; it < 4; it++) {
            const int i = tid + it * 256;
            const int r = i >> 3, c8 = i & 7;
            cp16(ab + (uint32_t)(r * 144 + c8 * 16), wsrc + (size_t)r * CPAD_ + kc * 64 + c8 * 8);
            cp16(bb + (uint32_t)(r * 144 + c8 * 16), bsrc + (size_t)r * CPAD_ + kc * 64 + c8 * 8);
        }
    };

    float c[2][8][4];
    #pragma unroll
    for (int mi = 0; mi < 2; mi++)
        #pragma unroll
        for (int nf = 0; nf < 8; nf++)
            #pragma unroll
            for (int q = 0; q < 4; q++) c[mi][nf][q] = 0.f;

    loadAB(0, 0); CP_COMMIT();
    loadAB(1, 1); CP_COMMIT();

    const int NK = CPAD_ / 64;  // 4
    for (int kc = 0; kc < NK; kc++) {
        if (kc + 1 < NK) CP_WAIT(1); else CP_WAIT(0);
        __syncthreads();
        if (kc + 2 < NK) { loadAB(kc + 2, (kc + 2) % 3); CP_COMMIT(); }
        const uint32_t Ab = sb + (uint32_t)((kc % 3) * STG64);
        const uint32_t Bb = Ab + AT64;
        #pragma unroll
        for (int s = 0; s < 4; s++) {
            uint32_t a[2][4];
            ldsm4(a[0], Ab + aoff + s * 32);
            ldsm4(a[1], Ab + aoff + 16 * 144 + s * 32);
            #pragma unroll
            for (int nfp = 0; nfp < 4; nfp++) {
                uint32_t bb4[4];
                ldsm4(bb4, Bb + boff + nfp * 16 * 144 + s * 32);
                mma16(c[0][nfp * 2],     a[0], bb4[0], bb4[1]);
                mma16(c[1][nfp * 2],     a[1], bb4[0], bb4[1]);
                mma16(c[0][nfp * 2 + 1], a[0], bb4[2], bb4[3]);
                mma16(c[1][nfp * 2 + 1], a[1], bb4[2], bb4[3]);
            }
        }
    }

    // Pos-channel rank-2 update (exact fp32): c += w[:,256]*gy(n) + w[:,257]*gx(n)
    #pragma unroll
    for (int mi = 0; mi < 2; mi++) {
        const int r0 = o0 + wm * 32 + mi * 16 + g;
        const float2 wp0 = *(const float2*)&wfull[(size_t)r0 * CIN_ + 256];
        const float2 wp1 = *(const float2*)&wfull[(size_t)(r0 + 8) * CIN_ + 256];
        #pragma unroll
        for (int nf = 0; nf < 8; nf++) {
            const int n = n0 + wn * 64 + nf * 8 + t4 * 2;
            const float gy0 = gyf(n),     gx0 = gxf(n);
            const float gy1 = gyf(n + 1), gx1 = gxf(n + 1);
            c[mi][nf][0] += wp0.x * gy0 + wp0.y * gx0;
            c[mi][nf][1] += wp0.x * gy1 + wp0.y * gx1;
            c[mi][nf][2] += wp1.x * gy0 + wp1.y * gx0;
            c[mi][nf][3] += wp1.x * gy1 + wp1.y * gx1;
        }
    }
    __syncthreads();

    float* Cs = (float*)sm;   // staging reuse: 128*132*4 = 67584 (< 110592 pipeline)
    if (sel < 2) {
        #pragma unroll
        for (int mi = 0; mi < 2; mi++) {
            const int m0 = wm * 32 + mi * 16;
            const float bv0 = bias[o0 + m0 + g];
            const float bv1 = bias[o0 + m0 + g + 8];
            #pragma unroll
            for (int nf = 0; nf < 8; nf++) {
                const int nn = wn * 64 + nf * 8 + t4 * 2;
                Cs[(nn)     * 132 + m0 + g]     = c[mi][nf][0] + bv0;
                Cs[(nn + 1) * 132 + m0 + g]     = c[mi][nf][1] + bv0;
                Cs[(nn)     * 132 + m0 + g + 8] = c[mi][nf][2] + bv1;
                Cs[(nn + 1) * 132 + m0 + g + 8] = c[mi][nf][3] + bv1;
            }
        }
        __syncthreads();
        bf16* dstbase = (sel == 0) ? g_q : g_k;
        #pragma unroll
        for (int it = 0; it < 16; it++) {
            const int i = tid + it * 256;
            const int nl = i >> 5, m4 = i & 31;
            const float4 cv = *(const float4*)&Cs[nl * 132 + m4 * 4];
            const int o = o0 + m4 * 4;
            const int h = o >> 6, d = o & 63;
            uint2 pk = make_uint2(pack2(cv.x, cv.y), pack2(cv.z, cv.w));
            *(uint2*)&dstbase[(((size_t)b * NH_ + h) * NTOK_ + n0 + nl) * FH_ + d] = pk;
        }
    } else {
        #pragma unroll
        for (int mi = 0; mi < 2; mi++) {
            #pragma unroll
            for (int half = 0; half < 2; half++) {
                const int m = wm * 32 + mi * 16 + g + half * 8;
                const int o = o0 + m;
                const int h = o >> 6, d = o & 63;
                const float bval = bias[o];
                bf16* dst = g_v + (((size_t)b * NH_ + h) * FH_ + d) * NTOK_ + n0;
                #pragma unroll
                for (int nf = 0; nf < 8; nf++) {
                    const int nn = wn * 64 + nf * 8 + t4 * 2;
                    *(uint32_t*)&dst[nn] = pack2(c[mi][nf][half * 2] + bval,
                                                 c[mi][nf][half * 2 + 1] + bval);
                }
            }
        }
    }
}

// ---------------------------------------------------------------------------
// Kernel 2: attention (R15 structure, unchanged).
#define KVSTG 9216
__global__ __launch_bounds__(128, 3) void attn_kernel() {
    extern __shared__ uint32_t sm[];
    const uint32_t sb = smem_u32(sm);
    const uint32_t KsB = sb, VsB = sb + 3 * KVSTG;

    const int tid = threadIdx.x;
    const int warp = tid >> 5, lane = tid & 31;
    const int g = lane >> 2, t4 = lane & 3;
    const int m0 = warp * 32;
    const int qt = blockIdx.x, h = blockIdx.y, b = blockIdx.z;
    const size_t hb = (size_t)(b * NH_ + h);
    const bf16* qsrc = g_q + hb * NTOK_ * FH_ + (size_t)qt * 128 * FH_;
    const bf16* ksrc = g_k + hb * NTOK_ * FH_;
    const bf16* vsrc = g_v + hb * FH_ * NTOK_;

    const uint32_t kvoff = (uint32_t)(((lane >> 4) * 8 + (lane & 7)) * 144
                                      + ((lane >> 3) & 1) * 16);

    uint32_t qf[2][4][4];
    #pragma unroll
    for (int mi = 0; mi < 2; mi++) {
        const uint32_t* q0 = (const uint32_t*)(qsrc + (size_t)(m0 + mi * 16 + g) * FH_);
        const uint32_t* q1 = (const uint32_t*)(qsrc + (size_t)(m0 + mi * 16 + g + 8) * FH_);
        #pragma unroll
        for (int s = 0; s < 4; s++) {
            qf[mi][s][0] = q0[s * 8 + t4];
            qf[mi][s][1] = q1[s * 8 + t4];
            qf[mi][s][2] = q0[s * 8 + t4 + 4];
            qf[mi][s][3] = q1[s * 8 + t4 + 4];
        }
    }

    auto loadKV = [&](int ck, int st) {
        const int c0 = ck * 64;
        #pragma unroll
        for (int it = 0; it < 4; it++) {
            const int i = tid + it * 128;
            const int r = i >> 3, c8 = i & 7;
            cp16(KsB + (uint32_t)(st * KVSTG + r * 144 + c8 * 16),
                 ksrc + (size_t)(c0 + r) * FH_ + c8 * 8);
            cp16(VsB + (uint32_t)(st * KVSTG + r * 144 + c8 * 16),
                 vsrc + (size_t)r * NTOK_ + c0 + c8 * 8);
        }
    };

    float oacc[2][8][4];
    #pragma unroll
    for (int mi = 0; mi < 2; mi++)
        #pragma unroll
        for (int nf = 0; nf < 8; nf++)
            #pragma unroll
            for (int q = 0; q < 4; q++) oacc[mi][nf][q] = 0.f;
    float lsum[2][2] = {{0.f, 0.f}, {0.f, 0.f}};

    loadKV(0, 0); CP_COMMIT();
    loadKV(1, 1); CP_COMMIT();

    const float SC = 0.125f * 1.4426950408889634f;

    for (int ck = 0; ck < 16; ck++) {
        if (ck + 1 < 16) CP_WAIT(1); else CP_WAIT(0);
        __syncthreads();
        if (ck + 2 < 16) { loadKV(ck + 2, (ck + 2) % 3); CP_COMMIT(); }
        const uint32_t Kb = KsB + (uint32_t)((ck % 3) * KVSTG);
        const uint32_t Vb = VsB + (uint32_t)((ck % 3) * KVSTG);

        #pragma unroll
        for (int half = 0; half < 2; half++) {
            float sc[2][4][4];
            #pragma unroll
            for (int mi = 0; mi < 2; mi++)
                #pragma unroll
                for (int nf = 0; nf < 4; nf++)
                    #pragma unroll
                    for (int q = 0; q < 4; q++) sc[mi][nf][q] = 0.f;
            #pragma unroll
            for (int s = 0; s < 4; s++) {
                #pragma unroll
                for (int nfp = 0; nfp < 2; nfp++) {
                    uint32_t bb4[4];
                    ldsm4(bb4, Kb + kvoff + (half * 2 + nfp) * 16 * 144 + s * 32);
                    mma16(sc[0][nfp * 2],     qf[0][s], bb4[0], bb4[1]);
                    mma16(sc[0][nfp * 2 + 1], qf[0][s], bb4[2], bb4[3]);
                    mma16(sc[1][nfp * 2],     qf[1][s], bb4[0], bb4[1]);
                    mma16(sc[1][nfp * 2 + 1], qf[1][s], bb4[2], bb4[3]);
                }
            }

            uint32_t pb[2][4][2];
            #pragma unroll
            for (int mi = 0; mi < 2; mi++)
                #pragma unroll
                for (int nf = 0; nf < 4; nf++) {
                    pb[mi][nf][0] = ex2_bf16x2(pack2(sc[mi][nf][0] * SC, sc[mi][nf][1] * SC));
                    pb[mi][nf][1] = ex2_bf16x2(pack2(sc[mi][nf][2] * SC, sc[mi][nf][3] * SC));
                }

            #pragma unroll
            for (int s2 = 0; s2 < 2; s2++) {
                const int sg = half * 2 + s2;
                const uint32_t pa0[4] = { pb[0][2 * s2][0], pb[0][2 * s2][1],
                                          pb[0][2 * s2 + 1][0], pb[0][2 * s2 + 1][1] };
                const uint32_t pa1[4] = { pb[1][2 * s2][0], pb[1][2 * s2][1],
                                          pb[1][2 * s2 + 1][0], pb[1][2 * s2 + 1][1] };
                #pragma unroll
                for (int nfp = 0; nfp < 4; nfp++) {
                    uint32_t bb4[4];
                    ldsm4(bb4, Vb + kvoff + nfp * 16 * 144 + sg * 32);
                    mma16(oacc[0][nfp * 2],     pa0, bb4[0], bb4[1]);
                    mma16(oacc[0][nfp * 2 + 1], pa0, bb4[2], bb4[3]);
                    mma16(oacc[1][nfp * 2],     pa1, bb4[0], bb4[1]);
                    mma16(oacc[1][nfp * 2 + 1], pa1, bb4[2], bb4[3]);
                }
            }

            #pragma unroll
            for (int mi = 0; mi < 2; mi++) {
                #pragma unroll
                for (int nf = 0; nf < 4; nf++) {
                    const float2 f0 = __bfloat1622float2(*(__nv_bfloat162*)&pb[mi][nf][0]);
                    const float2 f1 = __bfloat1622float2(*(__nv_bfloat162*)&pb[mi][nf][1]);
                    lsum[mi][0] += f0.x + f0.y;
                    lsum[mi][1] += f1.x + f1.y;
                }
            }
        }
    }

    #pragma unroll
    for (int mi = 0; mi < 2; mi++) {
        lsum[mi][0] += __shfl_xor_sync(0xffffffffu, lsum[mi][0], 1);
        lsum[mi][0] += __shfl_xor_sync(0xffffffffu, lsum[mi][0], 2);
        lsum[mi][1] += __shfl_xor_sync(0xffffffffu, lsum[mi][1], 1);
        lsum[mi][1] += __shfl_xor_sync(0xffffffffu, lsum[mi][1], 2);
    }

    #pragma unroll
    for (int mi = 0; mi < 2; mi++) {
        const float inv0 = 1.f / lsum[mi][0], inv1 = 1.f / lsum[mi][1];
        bf16* d0 = g_o + ((size_t)b * NTOK_ + qt * 128 + m0 + mi * 16 + g) * COUT_ + h * FH_;
        bf16* d1 = d0 + 8 * COUT_;
        #pragma unroll
        for (int nf = 0; nf < 8; nf++) {
            const int dd = nf * 8 + t4 * 2;
            *(uint32_t*)&d0[dd] = pack2(oacc[mi][nf][0] * inv0, oacc[mi][nf][1] * inv0);
            *(uint32_t*)&d1[dd] = pack2(oacc[mi][nf][2] * inv1, oacc[mi][nf][3] * inv1);
        }
    }
}

// ---------------------------------------------------------------------------
// Kernel 3: output projection + bias + residual. K-chunks 64 (8 chunks),
// 3-stage pipeline, ONE barrier per 64-K chunk.
__global__ __launch_bounds__(256, 2) void oproj_gemm(
    const float* __restrict__ x, const float* __restrict__ bo, float* __restrict__ out)
{
    extern __shared__ uint32_t sm[];
    const uint32_t sb = smem_u32(sm);

    const int tid = threadIdx.x;
    const int warp = tid >> 5, lane = tid & 31;
    const int g = lane >> 2, t4 = lane & 3;
    const int wm = warp & 3, wn = warp >> 2;
    const int nt = blockIdx.x, mt = blockIdx.y, b = blockIdx.z;
    const int o0 = mt * 128, n0 = nt * 128;
    const bf16* asrc = g_wo + (size_t)o0 * COUT_;
    const bf16* bsrc = g_o + ((size_t)b * NTOK_ + n0) * COUT_;

    const uint32_t aoff = (uint32_t)((wm * 32 + (lane & 15)) * 144 + (lane >> 4) * 16);
    const uint32_t boff = (uint32_t)((wn * 64 + (lane >> 4) * 8 + (lane & 7)) * 144
                                     + ((lane >> 3) & 1) * 16);

    auto loadAB = [&](int kc, int st) {
        const uint32_t ab = sb + (uint32_t)(st * STG64);
        const uint32_t bb = ab + AT64;
        #pragma unroll
        for (int it = 0; it < 4; it++) {
            const int i = tid + it * 256;
            const int r = i >> 3, c8 = i & 7;
            cp16(ab + (uint32_t)(r * 144 + c8 * 16), asrc + (size_t)r * COUT_ + kc * 64 + c8 * 8);
            cp16(bb + (uint32_t)(r * 144 + c8 * 16), bsrc + (size_t)r * COUT_ + kc * 64 + c8 * 8);
        }
    };

    float c[2][8][4];
    #pragma unroll
    for (int mi = 0; mi < 2; mi++)
        #pragma unroll
        for (int nf = 0; nf < 8; nf++)
            #pragma unroll
            for (int q = 0; q < 4; q++) c[mi][nf][q] = 0.f;

    loadAB(0, 0); CP_COMMIT();
    loadAB(1, 1); CP_COMMIT();

    const int NK = COUT_ / 64;  // 8
    for (int kc = 0; kc < NK; kc++) {
        if (kc + 1 < NK) CP_WAIT(1); else CP_WAIT(0);
        __syncthreads();
        if (kc + 2 < NK) { loadAB(kc + 2, (kc + 2) % 3); CP_COMMIT(); }
        const uint32_t Ab = sb + (uint32_t)((kc % 3) * STG64);
        const uint32_t Bb = Ab + AT64;
        #pragma unroll
        for (int s = 0; s < 4; s++) {
            uint32_t a[2][4];
            ldsm4(a[0], Ab + aoff + s * 32);
            ldsm4(a[1], Ab + aoff + 16 * 144 + s * 32);
            #pragma unroll
            for (int nfp = 0; nfp < 4; nfp++) {
                uint32_t bb4[4];
                ldsm4(bb4, Bb + boff + nfp * 16 * 144 + s * 32);
                mma16(c[0][nfp * 2],     a[0], bb4[0], bb4[1]);
                mma16(c[1][nfp * 2],     a[1], bb4[0], bb4[1]);
                mma16(c[0][nfp * 2 + 1], a[0], bb4[2], bb4[3]);
                mma16(c[1][nfp * 2 + 1], a[1], bb4[2], bb4[3]);
            }
        }
    }

    #pragma unroll
    for (int mi = 0; mi < 2; mi++) {
        #pragma unroll
        for (int half = 0; half < 2; half++) {
            const int m = o0 + wm * 32 + mi * 16 + g + half * 8;
            const float bval = bo[m];
            const float* xr = x + ((size_t)b * FIN_ + m) * NTOK_ + n0;
            float* outr = out + ((size_t)b * FIN_ + m) * NTOK_ + n0;
            #pragma unroll
            for (int nf = 0; nf < 8; nf++) {
                const int nn = wn * 64 + nf * 8 + t4 * 2;
                const float2 xv = *(const float2*)&xr[nn];
                *(float2*)&outr[nn] = make_float2(xv.x + bval + c[mi][nf][half * 2],
                                                  xv.y + bval + c[mi][nf][half * 2 + 1]);
            }
        }
    }
}

// ---------------------------------------------------------------------------
extern "C" void kernel_launch(void* const* d_in, const int* in_sizes, int n_in,
                              void* d_out, int out_size)
{
    const float* x  = (const float*)d_in[0];
    const float* wq = (const float*)d_in[1];
    const float* bq = (const float*)d_in[2];
    const float* wk = (const float*)d_in[3];
    const float* bk = (const float*)d_in[4];
    const float* wv = (const float*)d_in[5];
    const float* bv = (const float*)d_in[6];
    const float* wo = (const float*)d_in[7];
    const float* bo = (const float*)d_in[8];
    float* out = (float*)d_out;

    const int gemm_smem = 3 * STG64;             // 110592
    const int attn_smem = 6 * KVSTG;             // 55296
    cudaFuncSetAttribute(qkv_gemm,    cudaFuncAttributeMaxDynamicSharedMemorySize, gemm_smem);
    cudaFuncSetAttribute(oproj_gemm,  cudaFuncAttributeMaxDynamicSharedMemorySize, gemm_smem);
    cudaFuncSetAttribute(attn_kernel, cudaFuncAttributeMaxDynamicSharedMemorySize, attn_smem);

    prep_pack<<<512 + 1536 + 512, 256>>>(x, wq, wk, wv, wo);
    qkv_gemm<<<dim3(8, 12, 16), 256, gemm_smem>>>(wq, bq, wk, bk, wv, bv);
    attn_kernel<<<dim3(8, NH_, B_), 128, attn_smem>>>();
    oproj_gemm<<<dim3(8, 2, 16), 256, gemm_smem>>>(x, bo, out);
}

// round 17
// speedup vs baseline: 1.1078x; 1.0114x over previous
#include <cuda_runtime.h>
#include <cuda_bf16.h>
#include <cstdint>

#define B_    16
#define FIN_  256
#define NTOK_ 1024
#define NH_   8
#define FH_   64
#define CIN_  258
#define CPAD_ 256          // main GEMM K; pos channels handled in epilogue
#define COUT_ 512

typedef __nv_bfloat16 bf16;

// ---------------------------------------------------------------------------
__device__ bf16 g_t[B_ * NTOK_ * CPAD_];          // [b][n][c], c<256 (x only)
__device__ bf16 g_w[3 * COUT_ * CPAD_];           // packed qkv weights, first 256 cols
__device__ bf16 g_wo[FIN_ * COUT_];               // wo
__device__ bf16 g_q[B_ * NH_ * NTOK_ * FH_];      // [b][h][n][d]
__device__ bf16 g_k[B_ * NH_ * NTOK_ * FH_];      // [b][h][n][d]
__device__ bf16 g_v[B_ * NH_ * FH_ * NTOK_];      // [b][h][d][n]
__device__ bf16 g_o[B_ * NTOK_ * COUT_];          // [b][n][h*64+d]

// ---------------------------------------------------------------------------
__device__ __forceinline__ uint32_t smem_u32(const void* p) {
    uint32_t a;
    asm("{ .reg .u64 t; cvta.to.shared.u64 t, %1; cvt.u32.u64 %0, t; }" : "=r"(a) : "l"(p));
    return a;
}
__device__ __forceinline__ void cp16(uint32_t sdst, const void* gsrc) {
    asm volatile("cp.async.cg.shared.global [%0], [%1], 16;" :: "r"(sdst), "l"(gsrc));
}
#define CP_COMMIT() asm volatile("cp.async.commit_group;" ::: "memory")
#define CP_WAIT(n)  asm volatile("cp.async.wait_group %0;" :: "n"(n) : "memory")

__device__ __forceinline__ uint32_t pack2(float lo, float hi) {
    uint32_t r;
    asm("cvt.rn.bf16x2.f32 %0, %1, %2;" : "=r"(r) : "f"(hi), "f"(lo));
    return r;
}
__device__ __forceinline__ uint32_t ex2_bf16x2(uint32_t a) {
    uint32_t r;
    asm("ex2.approx.ftz.bf16x2 %0, %1;" : "=r"(r) : "r"(a));
    return r;
}
__device__ __forceinline__ void ldsm4(uint32_t r[4], uint32_t addr) {
    asm volatile("ldmatrix.sync.aligned.m8n8.x4.shared.b16 {%0,%1,%2,%3}, [%4];"
        : "=r"(r[0]), "=r"(r[1]), "=r"(r[2]), "=r"(r[3]) : "r"(addr));
}
__device__ __forceinline__ void mma16(float c[4], const uint32_t a[4], uint32_t b0, uint32_t b1) {
    asm volatile(
        "mma.sync.aligned.m16n8k16.row.col.f32.bf16.bf16.f32 "
        "{%0,%1,%2,%3}, {%4,%5,%6,%7}, {%8,%9}, {%0,%1,%2,%3};"
        : "+f"(c[0]), "+f"(c[1]), "+f"(c[2]), "+f"(c[3])
        : "r"(a[0]), "r"(a[1]), "r"(a[2]), "r"(a[3]), "r"(b0), "r"(b1));
}
__device__ __forceinline__ float gyf(int n) { return -1.f + (2.f / 31.f) * (float)(n >> 5); }
__device__ __forceinline__ float gxf(int n) { return -1.f + (2.f / 31.f) * (float)(n & 31); }

// ---------------------------------------------------------------------------
// Kernel 0 (fused): transpose x -> g_t (c<256 only), pack qkv weights, pack wo.
// All stores are packed bf16x2 (32-bit).
__global__ __launch_bounds__(256) void prep_pack(
    const float* __restrict__ x,
    const float* __restrict__ wq, const float* __restrict__ wk, const float* __restrict__ wv,
    const float* __restrict__ wo)
{
    const int blk = blockIdx.x;
    if (blk < 512) {
        __shared__ float tile[32][33];
        const int nt = blk & 31, b = blk >> 5;
        const int tx = threadIdx.x & 31, ty = threadIdx.x >> 5;
        const int n0 = nt * 32;
        for (int c0 = 0; c0 < FIN_; c0 += 32) {
            for (int ci = ty; ci < 32; ci += 8)
                tile[ci][tx] = x[((size_t)b * FIN_ + c0 + ci) * NTOK_ + n0 + tx];
            __syncthreads();
            #pragma unroll
            for (int i = threadIdx.x; i < 512; i += 256) {
                const int ni = i >> 4, cp = (i & 15) * 2;
                *(uint32_t*)&g_t[((size_t)b * NTOK_ + n0 + ni) * CPAD_ + c0 + cp] =
                    pack2(tile[cp][ni], tile[cp + 1][ni]);
            }
            __syncthreads();
        }
    } else if (blk < 512 + 768) {
        const int i2 = (blk - 512) * 256 + threadIdx.x;      // pair index, 3*512*128
        const int r = i2 >> 7, c = (i2 & 127) * 2;
        const int sel = r >> 9, o = r & 511;
        const float* w = (sel == 0) ? wq : ((sel == 1) ? wk : wv);
        *(uint32_t*)&g_w[(size_t)r * CPAD_ + c] =
            pack2(w[o * CIN_ + c], w[o * CIN_ + c + 1]);
    } else {
        const int i2 = (blk - 512 - 768) * 256 + threadIdx.x; // 256*512/2 pairs
        *(uint32_t*)&g_wo[(size_t)i2 * 2] = pack2(wo[i2 * 2], wo[i2 * 2 + 1]);
    }
}

// ---------------------------------------------------------------------------
// GEMM: CTA 128x128, 8 warps (4m x 2n), K-chunks 64 (4 k16 steps), pitch 144B,
// 3-stage cp.async pipeline, ONE barrier per 64-K chunk, ldmatrix fragments.
#define AT64  18432          // 128 rows x 144B
#define STG64 (2 * AT64)     // A + B per stage = 36864
__global__ __launch_bounds__(256, 2) void qkv_gemm(
    const float* __restrict__ wq, const float* __restrict__ bq,
    const float* __restrict__ wk, const float* __restrict__ bk,
    const float* __restrict__ wv, const float* __restrict__ bv)
{
    extern __shared__ uint32_t sm[];
    const uint32_t sb = smem_u32(sm);

    const int tid = threadIdx.x;
    const int warp = tid >> 5, lane = tid & 31;
    const int g = lane >> 2, t4 = lane & 3;
    const int wm = warp & 3, wn = warp >> 2;
    const int nt = blockIdx.x, mt = blockIdx.y, b = blockIdx.z;
    const int sel = mt >> 2;
    const int o0 = (mt & 3) * 128;
    const int n0 = nt * 128;
    const bf16* wsrc = g_w + (size_t)(sel * COUT_ + o0) * CPAD_;
    const bf16* bsrc = g_t + ((size_t)b * NTOK_ + n0) * CPAD_;
    const float* wfull = (sel == 0) ? wq : ((sel == 1) ? wk : wv);
    const float* bias  = (sel == 0) ? bq : ((sel == 1) ? bk : bv);

    const uint32_t aoff = (uint32_t)((wm * 32 + (lane & 15)) * 144 + (lane >> 4) * 16);
    const uint32_t boff = (uint32_t)((wn * 64 + (lane >> 4) * 8 + (lane & 7)) * 144
                                     + ((lane >> 3) & 1) * 16);

    auto loadAB = [&](int kc, int st) {
        const uint32_t ab = sb + (uint32_t)(st * STG64);
        const uint32_t bb = ab + AT64;
        #pragma unroll
        for (int it = 0; it < 4; it++) {
            const int i = tid + it * 256;
            const int r = i >> 3, c8 = i & 7;
            cp16(ab + (uint32_t)(r * 144 + c8 * 16), wsrc + (size_t)r * CPAD_ + kc * 64 + c8 * 8);
            cp16(bb + (uint32_t)(r * 144 + c8 * 16), bsrc + (size_t)r * CPAD_ + kc * 64 + c8 * 8);
        }
    };

    float c[2][8][4];
    #pragma unroll
    for (int mi = 0; mi < 2; mi++)
        #pragma unroll
        for (int nf = 0; nf < 8; nf++)
            #pragma unroll
            for (int q = 0; q < 4; q++) c[mi][nf][q] = 0.f;

#if __CUDA_ARCH__ >= 900
    cudaGridDependencySynchronize();
#endif

    loadAB(0, 0); CP_COMMIT();
    loadAB(1, 1); CP_COMMIT();

    const int NK = CPAD_ / 64;  // 4
    for (int kc = 0; kc < NK; kc++) {
        if (kc + 1 < NK) CP_WAIT(1); else CP_WAIT(0);
        __syncthreads();
        if (kc + 2 < NK) { loadAB(kc + 2, (kc + 2) % 3); CP_COMMIT(); }
        const uint32_t Ab = sb + (uint32_t)((kc % 3) * STG64);
        const uint32_t Bb = Ab + AT64;
        #pragma unroll
        for (int s = 0; s < 4; s++) {
            uint32_t a[2][4];
            ldsm4(a[0], Ab + aoff + s * 32);
            ldsm4(a[1], Ab + aoff + 16 * 144 + s * 32);
            #pragma unroll
            for (int nfp = 0; nfp < 4; nfp++) {
                uint32_t bb4[4];
                ldsm4(bb4, Bb + boff + nfp * 16 * 144 + s * 32);
                mma16(c[0][nfp * 2],     a[0], bb4[0], bb4[1]);
                mma16(c[1][nfp * 2],     a[1], bb4[0], bb4[1]);
                mma16(c[0][nfp * 2 + 1], a[0], bb4[2], bb4[3]);
                mma16(c[1][nfp * 2 + 1], a[1], bb4[2], bb4[3]);
            }
        }
    }

    // Pos-channel rank-2 update (exact fp32)
    #pragma unroll
    for (int mi = 0; mi < 2; mi++) {
        const int r0 = o0 + wm * 32 + mi * 16 + g;
        const float2 wp0 = *(const float2*)&wfull[(size_t)r0 * CIN_ + 256];
        const float2 wp1 = *(const float2*)&wfull[(size_t)(r0 + 8) * CIN_ + 256];
        #pragma unroll
        for (int nf = 0; nf < 8; nf++) {
            const int n = n0 + wn * 64 + nf * 8 + t4 * 2;
            const float gy0 = gyf(n),     gx0 = gxf(n);
            const float gy1 = gyf(n + 1), gx1 = gxf(n + 1);
            c[mi][nf][0] += wp0.x * gy0 + wp0.y * gx0;
            c[mi][nf][1] += wp0.x * gy1 + wp0.y * gx1;
            c[mi][nf][2] += wp1.x * gy0 + wp1.y * gx0;
            c[mi][nf][3] += wp1.x * gy1 + wp1.y * gx1;
        }
    }
    __syncthreads();

    float* Cs = (float*)sm;   // staging reuse: 128*132*4 = 67584 (< 110592 pipeline)
    if (sel < 2) {
        #pragma unroll
        for (int mi = 0; mi < 2; mi++) {
            const int m0 = wm * 32 + mi * 16;
            const float bv0 = bias[o0 + m0 + g];
            const float bv1 = bias[o0 + m0 + g + 8];
            #pragma unroll
            for (int nf = 0; nf < 8; nf++) {
                const int nn = wn * 64 + nf * 8 + t4 * 2;
                Cs[(nn)     * 132 + m0 + g]     = c[mi][nf][0] + bv0;
                Cs[(nn + 1) * 132 + m0 + g]     = c[mi][nf][1] + bv0;
                Cs[(nn)     * 132 + m0 + g + 8] = c[mi][nf][2] + bv1;
                Cs[(nn + 1) * 132 + m0 + g + 8] = c[mi][nf][3] + bv1;
            }
        }
        __syncthreads();
        bf16* dstbase = (sel == 0) ? g_q : g_k;
        #pragma unroll
        for (int it = 0; it < 16; it++) {
            const int i = tid + it * 256;
            const int nl = i >> 5, m4 = i & 31;
            const float4 cv = *(const float4*)&Cs[nl * 132 + m4 * 4];
            const int o = o0 + m4 * 4;
            const int h = o >> 6, d = o & 63;
            uint2 pk = make_uint2(pack2(cv.x, cv.y), pack2(cv.z, cv.w));
            *(uint2*)&dstbase[(((size_t)b * NH_ + h) * NTOK_ + n0 + nl) * FH_ + d] = pk;
        }
    } else {
        #pragma unroll
        for (int mi = 0; mi < 2; mi++) {
            #pragma unroll
            for (int half = 0; half < 2; half++) {
                const int m = wm * 32 + mi * 16 + g + half * 8;
                const int o = o0 + m;
                const int h = o >> 6, d = o & 63;
                const float bval = bias[o];
                bf16* dst = g_v + (((size_t)b * NH_ + h) * FH_ + d) * NTOK_ + n0;
                #pragma unroll
                for (int nf = 0; nf < 8; nf++) {
                    const int nn = wn * 64 + nf * 8 + t4 * 2;
                    *(uint32_t*)&dst[nn] = pack2(c[mi][nf][half * 2] + bval,
                                                 c[mi][nf][half * 2 + 1] + bval);
                }
            }
        }
    }
}

// ---------------------------------------------------------------------------
// Kernel 2: attention (R15 structure).
#define KVSTG 9216
__global__ __launch_bounds__(128, 3) void attn_kernel() {
    extern __shared__ uint32_t sm[];
    const uint32_t sb = smem_u32(sm);
    const uint32_t KsB = sb, VsB = sb + 3 * KVSTG;

    const int tid = threadIdx.x;
    const int warp = tid >> 5, lane = tid & 31;
    const int g = lane >> 2, t4 = lane & 3;
    const int m0 = warp * 32;
    const int qt = blockIdx.x, h = blockIdx.y, b = blockIdx.z;
    const size_t hb = (size_t)(b * NH_ + h);
    const bf16* qsrc = g_q + hb * NTOK_ * FH_ + (size_t)qt * 128 * FH_;
    const bf16* ksrc = g_k + hb * NTOK_ * FH_;
    const bf16* vsrc = g_v + hb * FH_ * NTOK_;

    const uint32_t kvoff = (uint32_t)(((lane >> 4) * 8 + (lane & 7)) * 144
                                      + ((lane >> 3) & 1) * 16);

#if __CUDA_ARCH__ >= 900
    cudaGridDependencySynchronize();
#endif

    uint32_t qf[2][4][4];
    #pragma unroll
    for (int mi = 0; mi < 2; mi++) {
        const uint32_t* q0 = (const uint32_t*)(qsrc + (size_t)(m0 + mi * 16 + g) * FH_);
        const uint32_t* q1 = (const uint32_t*)(qsrc + (size_t)(m0 + mi * 16 + g + 8) * FH_);
        #pragma unroll
        for (int s = 0; s < 4; s++) {
            qf[mi][s][0] = q0[s * 8 + t4];
            qf[mi][s][1] = q1[s * 8 + t4];
            qf[mi][s][2] = q0[s * 8 + t4 + 4];
            qf[mi][s][3] = q1[s * 8 + t4 + 4];
        }
    }

    auto loadKV = [&](int ck, int st) {
        const int c0 = ck * 64;
        #pragma unroll
        for (int it = 0; it < 4; it++) {
            const int i = tid + it * 128;
            const int r = i >> 3, c8 = i & 7;
            cp16(KsB + (uint32_t)(st * KVSTG + r * 144 + c8 * 16),
                 ksrc + (size_t)(c0 + r) * FH_ + c8 * 8);
            cp16(VsB + (uint32_t)(st * KVSTG + r * 144 + c8 * 16),
                 vsrc + (size_t)r * NTOK_ + c0 + c8 * 8);
        }
    };

    float oacc[2][8][4];
    #pragma unroll
    for (int mi = 0; mi < 2; mi++)
        #pragma unroll
        for (int nf = 0; nf < 8; nf++)
            #pragma unroll
            for (int q = 0; q < 4; q++) oacc[mi][nf][q] = 0.f;
    float lsum[2][2] = {{0.f, 0.f}, {0.f, 0.f}};

    loadKV(0, 0); CP_COMMIT();
    loadKV(1, 1); CP_COMMIT();

    const float SC = 0.125f * 1.4426950408889634f;

    for (int ck = 0; ck < 16; ck++) {
        if (ck + 1 < 16) CP_WAIT(1); else CP_WAIT(0);
        __syncthreads();
        if (ck + 2 < 16) { loadKV(ck + 2, (ck + 2) % 3); CP_COMMIT(); }
        const uint32_t Kb = KsB + (uint32_t)((ck % 3) * KVSTG);
        const uint32_t Vb = VsB + (uint32_t)((ck % 3) * KVSTG);

        #pragma unroll
        for (int half = 0; half < 2; half++) {
            float sc[2][4][4];
            #pragma unroll
            for (int mi = 0; mi < 2; mi++)
                #pragma unroll
                for (int nf = 0; nf < 4; nf++)
                    #pragma unroll
                    for (int q = 0; q < 4; q++) sc[mi][nf][q] = 0.f;
            #pragma unroll
            for (int s = 0; s < 4; s++) {
                #pragma unroll
                for (int nfp = 0; nfp < 2; nfp++) {
                    uint32_t bb4[4];
                    ldsm4(bb4, Kb + kvoff + (half * 2 + nfp) * 16 * 144 + s * 32);
                    mma16(sc[0][nfp * 2],     qf[0][s], bb4[0], bb4[1]);
                    mma16(sc[0][nfp * 2 + 1], qf[0][s], bb4[2], bb4[3]);
                    mma16(sc[1][nfp * 2],     qf[1][s], bb4[0], bb4[1]);
                    mma16(sc[1][nfp * 2 + 1], qf[1][s], bb4[2], bb4[3]);
                }
            }

            uint32_t pb[2][4][2];
            #pragma unroll
            for (int mi = 0; mi < 2; mi++)
                #pragma unroll
                for (int nf = 0; nf < 4; nf++) {
                    pb[mi][nf][0] = ex2_bf16x2(pack2(sc[mi][nf][0] * SC, sc[mi][nf][1] * SC));
                    pb[mi][nf][1] = ex2_bf16x2(pack2(sc[mi][nf][2] * SC, sc[mi][nf][3] * SC));
                }

            #pragma unroll
            for (int s2 = 0; s2 < 2; s2++) {
                const int sg = half * 2 + s2;
                const uint32_t pa0[4] = { pb[0][2 * s2][0], pb[0][2 * s2][1],
                                          pb[0][2 * s2 + 1][0], pb[0][2 * s2 + 1][1] };
                const uint32_t pa1[4] = { pb[1][2 * s2][0], pb[1][2 * s2][1],
                                          pb[1][2 * s2 + 1][0], pb[1][2 * s2 + 1][1] };
                #pragma unroll
                for (int nfp = 0; nfp < 4; nfp++) {
                    uint32_t bb4[4];
                    ldsm4(bb4, Vb + kvoff + nfp * 16 * 144 + sg * 32);
                    mma16(oacc[0][nfp * 2],     pa0, bb4[0], bb4[1]);
                    mma16(oacc[0][nfp * 2 + 1], pa0, bb4[2], bb4[3]);
                    mma16(oacc[1][nfp * 2],     pa1, bb4[0], bb4[1]);
                    mma16(oacc[1][nfp * 2 + 1], pa1, bb4[2], bb4[3]);
                }
            }

            #pragma unroll
            for (int mi = 0; mi < 2; mi++) {
                #pragma unroll
                for (int nf = 0; nf < 4; nf++) {
                    const float2 f0 = __bfloat1622float2(*(__nv_bfloat162*)&pb[mi][nf][0]);
                    const float2 f1 = __bfloat1622float2(*(__nv_bfloat162*)&pb[mi][nf][1]);
                    lsum[mi][0] += f0.x + f0.y;
                    lsum[mi][1] += f1.x + f1.y;
                }
            }
        }
    }

    #pragma unroll
    for (int mi = 0; mi < 2; mi++) {
        lsum[mi][0] += __shfl_xor_sync(0xffffffffu, lsum[mi][0], 1);
        lsum[mi][0] += __shfl_xor_sync(0xffffffffu, lsum[mi][0], 2);
        lsum[mi][1] += __shfl_xor_sync(0xffffffffu, lsum[mi][1], 1);
        lsum[mi][1] += __shfl_xor_sync(0xffffffffu, lsum[mi][1], 2);
    }

    #pragma unroll
    for (int mi = 0; mi < 2; mi++) {
        const float inv0 = 1.f / lsum[mi][0], inv1 = 1.f / lsum[mi][1];
        bf16* d0 = g_o + ((size_t)b * NTOK_ + qt * 128 + m0 + mi * 16 + g) * COUT_ + h * FH_;
        bf16* d1 = d0 + 8 * COUT_;
        #pragma unroll
        for (int nf = 0; nf < 8; nf++) {
            const int dd = nf * 8 + t4 * 2;
            *(uint32_t*)&d0[dd] = pack2(oacc[mi][nf][0] * inv0, oacc[mi][nf][1] * inv0);
            *(uint32_t*)&d1[dd] = pack2(oacc[mi][nf][2] * inv1, oacc[mi][nf][3] * inv1);
        }
    }
}

// ---------------------------------------------------------------------------
// Kernel 3: output projection + bias + residual. K-chunks 64 (8 chunks).
__global__ __launch_bounds__(256, 2) void oproj_gemm(
    const float* __restrict__ x, const float* __restrict__ bo, float* __restrict__ out)
{
    extern __shared__ uint32_t sm[];
    const uint32_t sb = smem_u32(sm);

    const int tid = threadIdx.x;
    const int warp = tid >> 5, lane = tid & 31;
    const int g = lane >> 2, t4 = lane & 3;
    const int wm = warp & 3, wn = warp >> 2;
    const int nt = blockIdx.x, mt = blockIdx.y, b = blockIdx.z;
    const int o0 = mt * 128, n0 = nt * 128;
    const bf16* asrc = g_wo + (size_t)o0 * COUT_;
    const bf16* bsrc = g_o + ((size_t)b * NTOK_ + n0) * COUT_;

    const uint32_t aoff = (uint32_t)((wm * 32 + (lane & 15)) * 144 + (lane >> 4) * 16);
    const uint32_t boff = (uint32_t)((wn * 64 + (lane >> 4) * 8 + (lane & 7)) * 144
                                     + ((lane >> 3) & 1) * 16);

    auto loadAB = [&](int kc, int st) {
        const uint32_t ab = sb + (uint32_t)(st * STG64);
        const uint32_t bb = ab + AT64;
        #pragma unroll
        for (int it = 0; it < 4; it++) {
            const int i = tid + it * 256;
            const int r = i >> 3, c8 = i & 7;
            cp16(ab + (uint32_t)(r * 144 + c8 * 16), asrc + (size_t)r * COUT_ + kc * 64 + c8 * 8);
            cp16(bb + (uint32_t)(r * 144 + c8 * 16), bsrc + (size_t)r * COUT_ + kc * 64 + c8 * 8);
        }
    };

    float c[2][8][4];
    #pragma unroll
    for (int mi = 0; mi < 2; mi++)
        #pragma unroll
        for (int nf = 0; nf < 8; nf++)
            #pragma unroll
            for (int q = 0; q < 4; q++) c[mi][nf][q] = 0.f;

#if __CUDA_ARCH__ >= 900
    cudaGridDependencySynchronize();
#endif

    loadAB(0, 0); CP_COMMIT();
    loadAB(1, 1); CP_COMMIT();

    const int NK = COUT_ / 64;  // 8
    for (int kc = 0; kc < NK; kc++) {
        if (kc + 1 < NK) CP_WAIT(1); else CP_WAIT(0);
        __syncthreads();
        if (kc + 2 < NK) { loadAB(kc + 2, (kc + 2) % 3); CP_COMMIT(); }
        const uint32_t Ab = sb + (uint32_t)((kc % 3) * STG64);
        const uint32_t Bb = Ab + AT64;
        #pragma unroll
        for (int s = 0; s < 4; s++) {
            uint32_t a[2][4];
            ldsm4(a[0], Ab + aoff + s * 32);
            ldsm4(a[1], Ab + aoff + 16 * 144 + s * 32);
            #pragma unroll
            for (int nfp = 0; nfp < 4; nfp++) {
                uint32_t bb4[4];
                ldsm4(bb4, Bb + boff + nfp * 16 * 144 + s * 32);
                mma16(c[0][nfp * 2],     a[0], bb4[0], bb4[1]);
                mma16(c[1][nfp * 2],     a[1], bb4[0], bb4[1]);
                mma16(c[0][nfp * 2 + 1], a[0], bb4[2], bb4[3]);
                mma16(c[1][nfp * 2 + 1], a[1], bb4[2], bb4[3]);
            }
        }
    }

    #pragma unroll
    for (int mi = 0; mi < 2; mi++) {
        #pragma unroll
        for (int half = 0; half < 2; half++) {
            const int m = o0 + wm * 32 + mi * 16 + g + half * 8;
            const float bval = bo[m];
            const float* xr = x + ((size_t)b * FIN_ + m) * NTOK_ + n0;
            float* outr = out + ((size_t)b * FIN_ + m) * NTOK_ + n0;
            #pragma unroll
            for (int nf = 0; nf < 8; nf++) {
                const int nn = wn * 64 + nf * 8 + t4 * 2;
                const float2 xv = *(const float2*)&xr[nn];
                *(float2*)&outr[nn] = make_float2(xv.x + bval + c[mi][nf][half * 2],
                                                  xv.y + bval + c[mi][nf][half * 2 + 1]);
            }
        }
    }
}

// ---------------------------------------------------------------------------
static inline void launch_pdl(const void* fn, dim3 grid, dim3 block, size_t smem,
                              void** args)
{
    cudaLaunchConfig_t cfg = {};
    cfg.gridDim = grid;
    cfg.blockDim = block;
    cfg.dynamicSmemBytes = smem;
    cfg.stream = 0;
    cudaLaunchAttribute attr[1];
    attr[0].id = cudaLaunchAttributeProgrammaticStreamSerialization;
    attr[0].val.programmaticStreamSerializationAllowed = 1;
    cfg.attrs = attr;
    cfg.numAttrs = 1;
    cudaLaunchKernelExC(&cfg, fn, args);
}

extern "C" void kernel_launch(void* const* d_in, const int* in_sizes, int n_in,
                              void* d_out, int out_size)
{
    const float* x  = (const float*)d_in[0];
    const float* wq = (const float*)d_in[1];
    const float* bq = (const float*)d_in[2];
    const float* wk = (const float*)d_in[3];
    const float* bk = (const float*)d_in[4];
    const float* wv = (const float*)d_in[5];
    const float* bv = (const float*)d_in[6];
    const float* wo = (const float*)d_in[7];
    const float* bo = (const float*)d_in[8];
    float* out = (float*)d_out;

    const int gemm_smem = 3 * STG64;             // 110592
    const int attn_smem = 6 * KVSTG;             // 55296
    cudaFuncSetAttribute(qkv_gemm,    cudaFuncAttributeMaxDynamicSharedMemorySize, gemm_smem);
    cudaFuncSetAttribute(oproj_gemm,  cudaFuncAttributeMaxDynamicSharedMemorySize, gemm_smem);
    cudaFuncSetAttribute(attn_kernel, cudaFuncAttributeMaxDynamicSharedMemorySize, attn_smem);

    prep_pack<<<512 + 768 + 256, 256>>>(x, wq, wk, wv, wo);

    {
        void* args[] = { (void*)&wq, (void*)&bq, (void*)&wk, (void*)&bk, (void*)&wv, (void*)&bv };
        launch_pdl((const void*)qkv_gemm, dim3(8, 12, 16), dim3(256), gemm_smem, args);
    }
    {
        void* args[] = { nullptr };
        launch_pdl((const void*)attn_kernel, dim3(8, NH_, B_), dim3(128), attn_smem, args);
    }
    {
        void* args[] = { (void*)&x, (void*)&bo, (void*)&out };
        launch_pdl((const void*)oproj_gemm, dim3(8, 2, 16), dim3(256), gemm_smem, args);
    }
}